// round 10
// baseline (speedup 1.0000x reference)
#include <cuda_runtime.h>
#include <cuda_bf16.h>
#include <cstdint>

#define CC   96
#define LL   2304
#define NBQ  64
#define PXQ  36864
#define NPL  24
#define NSEG 8
#define TCH  18

// ---------------- static scratch ----------------
__device__ float g_a   [NBQ*LL*CC];
__device__ float g_zin [NBQ*LL*CC];
__device__ float g_vf  [NBQ*LL*CC];
__device__ float g_xdbl[NBQ*4*NPL*LL];
__device__ float g_y   [NBQ*LL*CC];
__device__ float g_yo  [NBQ*LL*CC];
__device__ float g_ysum[NBQ*CC];
__device__ float g_att [NBQ*CC];
__device__ float g_sd  [NBQ*4*NSEG*CC];
__device__ float g_hfin[NBQ*4*NSEG*CC*8];
__device__ float g_hin [NBQ*4*NSEG*CC*8];

__device__ __forceinline__ float siluf(float v){ return v * (1.f/(1.f+__expf(-v))); }

__device__ __forceinline__ void fma2(unsigned long long &acc, unsigned long long a, unsigned long long b){
    asm("fma.rn.f32x2 %0,%1,%2,%0;" : "+l"(acc) : "l"(a), "l"(b));
}
__device__ __forceinline__ unsigned long long pack2(float v){
    unsigned long long r; asm("mov.b64 %0,{%1,%1};" : "=l"(r) : "f"(v)); return r;
}
__device__ __forceinline__ float2 unpack2(unsigned long long v){
    float2 r; asm("mov.b64 {%0,%1},%2;" : "=f"(r.x), "=f"(r.y) : "l"(v)); return r;
}
__device__ __forceinline__ void cpasync16(void* dst, const void* src){
    unsigned d = (unsigned)__cvta_generic_to_shared(dst);
    asm volatile("cp.async.ca.shared.global [%0],[%1],16;" :: "r"(d), "l"(src));
}

// =============== K1: LN + BOTH 1x1 convs, 64px x 192oc, 8px/thread ===============
// block 128 = 8 tp(8px) x 16 tc(12oc via 6 pairs; tc<8 conv0, tc>=8 conv1)
#define X1S 68
#define W1S 198
__global__ __launch_bounds__(128,2) void k1_gemm(const float* __restrict__ x,
                                                 const float* __restrict__ lg, const float* __restrict__ lb,
                                                 const float* __restrict__ p1w, const float* __restrict__ p1b,
                                                 const float* __restrict__ p2w, const float* __restrict__ p2b)
{
    extern __shared__ float sm[];
    float* Xs = sm;                 // [96][68]
    float* Ws = sm + 96*X1S;        // [96][198]
    __shared__ float mu[64], rs[64];
    __shared__ float b0s[96], b1s[96];
    int q = blockIdx.y, P0 = blockIdx.x*64;
    int bb = P0 / LL, l0 = P0 % LL;
    int qh=(q>>1)*48, qw=(q&1)*48;
    int tid = threadIdx.x;
    const float* xb = x + (size_t)bb*884736 + (size_t)qh*96 + qw;
    // x tile: p fastest -> conflict-free STS, coalesced-ish LDG
    for (int i=tid; i<96*64; i+=128){
        int c=i>>6, p=i&63;
        int l=l0+p, h=l/48, w=l%48;
        Xs[c*X1S+p] = xb[(size_t)c*9216 + h*96 + w];
    }
    const float* W0 = p1w + (size_t)q*9216;
    const float* W1 = p2w + (size_t)q*9216;
    for (int i=tid; i<9216; i+=128){
        int d=i/96, c=i%96;
        Ws[c*W1S+d]    = W0[i];
        Ws[c*W1S+96+d] = W1[i];
    }
    for (int i=tid; i<96; i+=128){ b0s[i]=p1b[q*96+i]; b1s[i]=p2b[q*96+i]; }
    __syncthreads();
    // per-pixel LN stats: 2 threads per px
    {
        int px = tid>>1, part = tid&1;
        float s=0.f, ss=0.f;
        const float* col = Xs + px;
        #pragma unroll 8
        for (int cc=part*48; cc<part*48+48; cc++){ float v=col[cc*X1S]; s+=v; ss+=v*v; }
        s  += __shfl_xor_sync(0xffffffffu, s, 1);
        ss += __shfl_xor_sync(0xffffffffu, ss, 1);
        if (part==0){
            float m = s*(1.f/96.f);
            mu[px]=m; rs[px]=rsqrtf(ss*(1.f/96.f)-m*m+1e-6f);
        }
    }
    __syncthreads();
    for (int i=tid; i<96*64; i+=128){
        int c=i>>6, p=i&63;
        Xs[c*X1S+p] = (Xs[c*X1S+p]-mu[p])*rs[p]*lg[q*96+c] + lb[q*96+c];
    }
    __syncthreads();
    int tp = tid & 7, tc = tid >> 3;
    unsigned long long acc[6][8];
    #pragma unroll
    for (int j=0;j<6;j++)
        #pragma unroll
        for (int p=0;p<8;p++) acc[j][p]=0ull;
    const float* xbq = Xs + 8*tp;
    const float* wbq = Ws + 12*tc;
    #pragma unroll 2
    for (int k=0;k<96;k++){
        float4 xv0 = *(const float4*)(xbq + k*X1S);
        float4 xv1 = *(const float4*)(xbq + k*X1S + 4);
        unsigned long long xd[8];
        xd[0]=pack2(xv0.x); xd[1]=pack2(xv0.y); xd[2]=pack2(xv0.z); xd[3]=pack2(xv0.w);
        xd[4]=pack2(xv1.x); xd[5]=pack2(xv1.y); xd[6]=pack2(xv1.z); xd[7]=pack2(xv1.w);
        const unsigned long long* wp = (const unsigned long long*)(wbq + k*W1S);
        #pragma unroll
        for (int j=0;j<6;j++){
            unsigned long long wv = wp[j];
            #pragma unroll
            for (int p=0;p<8;p++) fma2(acc[j][p], wv, xd[p]);
        }
    }
    __syncthreads();
    float* sout = sm;                 // [64][100]
    // ---- conv0 (tc<8) ----
    if (tc < 8){
        #pragma unroll
        for (int j=0;j<6;j++){
            int oc = 12*tc + 2*j;
            #pragma unroll
            for (int p=0;p<8;p++){
                float2 v = unpack2(acc[j][p]);
                sout[(size_t)(8*tp+p)*100 + oc    ] = v.x;
                sout[(size_t)(8*tp+p)*100 + oc + 1] = v.y;
            }
        }
    }
    __syncthreads();
    {
        float* dst = g_a + ((size_t)q*PXQ + P0)*96;
        for (int i=tid; i<64*96; i+=128){
            int p=i/96, oc=i%96;
            dst[i] = siluf(sout[p*100+oc] + b0s[oc]);
        }
    }
    __syncthreads();
    // ---- conv1 (tc>=8) ----
    if (tc >= 8){
        #pragma unroll
        for (int j=0;j<6;j++){
            int oc = 12*(tc-8) + 2*j;
            #pragma unroll
            for (int p=0;p<8;p++){
                float2 v = unpack2(acc[j][p]);
                sout[(size_t)(8*tp+p)*100 + oc    ] = v.x;
                sout[(size_t)(8*tp+p)*100 + oc + 1] = v.y;
            }
        }
    }
    __syncthreads();
    {
        float* dst = g_zin + ((size_t)q*PXQ + P0)*96;
        for (int i=tid; i<64*96; i+=128){
            int p=i/96, oc=i%96;
            dst[i] = sout[p*100+oc] + b1s[oc];
        }
    }
}

// =============== K2: depthwise 3x3 + bias + silu + pre-transform; zeros g_y ===============
__global__ __launch_bounds__(256) void k2_dw(const float* __restrict__ dww, const float* __restrict__ dwb,
                                             const int* __restrict__ bidx)
{
    extern __shared__ float rows[];
    __shared__ float wsm[96*9];
    __shared__ float bsm[96];
    int qb = blockIdx.x, q = qb>>4, hr = blockIdx.y;
    if (blockIdx.x==0 && blockIdx.y==0)
        for (int i=threadIdx.x; i<NBQ*CC; i+=256) g_ysum[i]=0.f;
    {
        float* yz = g_y + ((size_t)qb*LL + hr*48)*96;
        for (int i=threadIdx.x; i<48*96; i+=256) yz[i]=0.f;
    }
    for (int i=threadIdx.x; i<96*9; i+=256) wsm[i]=dww[q*96*9 + i];
    for (int i=threadIdx.x; i<96;   i+=256) bsm[i]=dwb[q*96 + i];
    for (int dy=0; dy<3; dy++){
        int hh = hr-1+dy;
        if (hh>=0 && hh<48){
            const float* src = g_zin + ((size_t)qb*LL + hh*48)*96;
            for (int i=threadIdx.x; i<48*96; i+=256) rows[dy*4608+i]=src[i];
        } else {
            for (int i=threadIdx.x; i<48*96; i+=256) rows[dy*4608+i]=0.f;
        }
    }
    __syncthreads();
    bool even = ((bidx[0] & 1) == 0);
    for (int i=threadIdx.x; i<48*96; i+=256){
        int w=i/96, c=i%96;
        float acc = bsm[c];
        #pragma unroll
        for (int dy=0; dy<3; dy++){
            #pragma unroll
            for (int dx=0; dx<3; dx++){
                int ww = w+dx-1;
                if (ww>=0 && ww<48) acc += wsm[c*9+dy*3+dx]*rows[dy*4608 + ww*96 + c];
            }
        }
        float z = siluf(acc);
        int pf = even ? (w*48+hr) : ((47-hr)*48+(47-w));
        g_vf[((size_t)qb*LL + pf)*96 + c] = z;
    }
}

// =============== K3: x-projection GEMM, 8px/thread ===============
// block 128 = 16 tp(8px) x 8 tc(6oc via 3 pairs). Tile 128px x 48oc.
#define K3XS 132
#define K3WS 50
__global__ __launch_bounds__(128,3) void k3_proj(const float* __restrict__ xprojw)
{
    extern __shared__ float sm[];
    float* Xs = sm;                // [96][132]
    float* Ws = sm + 96*K3XS;      // [96][50]
    int q = blockIdx.z, src = blockIdx.y, P0 = blockIdx.x*128;
    int b_img = P0 / LL;
    int l0 = P0 % LL;
    int tid = threadIdx.x;
    const float* vbase = g_vf + (size_t)(q*16 + b_img)*LL*96;
    for (int i=tid; i<128*96; i+=128){
        int p=i/96, c=i%96;
        int l = l0 + p;
        int row = src ? ((l%48)*48 + l/48) : l;
        Xs[c*K3XS+p] = vbase[(size_t)row*96 + c];
    }
    for (int i=tid; i<48*96; i+=128){
        int oc=i/96, kk=i%96;
        float v=0.f;
        if (oc<44){
            int k = (oc<22)? src : src+2;
            int d = (oc<22)? oc : oc-22;
            v = xprojw[(((size_t)q*4 + k)*22 + d)*96 + kk];
        }
        Ws[kk*K3WS+oc]=v;
    }
    __syncthreads();
    int tp = tid & 15, tc = tid >> 4;
    unsigned long long acc[3][8];
    #pragma unroll
    for (int j=0;j<3;j++)
        #pragma unroll
        for (int p=0;p<8;p++) acc[j][p]=0ull;
    const float* xbq = Xs + 8*tp;
    const float* wbq = Ws + 6*tc;
    #pragma unroll 2
    for (int k=0;k<96;k++){
        float4 xv0 = *(const float4*)(xbq + k*K3XS);
        float4 xv1 = *(const float4*)(xbq + k*K3XS + 4);
        unsigned long long xd[8];
        xd[0]=pack2(xv0.x); xd[1]=pack2(xv0.y); xd[2]=pack2(xv0.z); xd[3]=pack2(xv0.w);
        xd[4]=pack2(xv1.x); xd[5]=pack2(xv1.y); xd[6]=pack2(xv1.z); xd[7]=pack2(xv1.w);
        const unsigned long long* wp = (const unsigned long long*)(wbq + k*K3WS);
        #pragma unroll
        for (int j=0;j<3;j++){
            unsigned long long wv = wp[j];
            #pragma unroll
            for (int p=0;p<8;p++) fma2(acc[j][p], wv, xd[p]);
        }
    }
    int qb = q*16 + b_img;
    int lw = l0 + 8*tp;
    #pragma unroll
    for (int j=0;j<3;j++){
        float2 v[8];
        #pragma unroll
        for (int p=0;p<8;p++) v[p]=unpack2(acc[j][p]);
        #pragma unroll
        for (int h=0; h<2; h++){
            int oc = 6*tc + 2*j + h;
            if (oc>=44) continue;
            int kdir = (oc<22)? src : src+2;
            int d    = (oc<22)? oc : oc-22;
            int plane= (d<6)? d : d+2;
            float* dst = g_xdbl + (((size_t)qb*4 + kdir)*NPL + plane)*LL + lw;
            if (h){
                *(float4*)(dst)   = make_float4(v[0].y,v[1].y,v[2].y,v[3].y);
                *(float4*)(dst+4) = make_float4(v[4].y,v[5].y,v[6].y,v[7].y);
            } else {
                *(float4*)(dst)   = make_float4(v[0].x,v[1].x,v[2].x,v[3].x);
                *(float4*)(dst+4) = make_float4(v[4].x,v[5].x,v[6].x,v[7].x);
            }
        }
    }
}

// =============== Scan pass A: segmented local scan (h0=0) ===============
__global__ __launch_bounds__(96) void k_scan_seg(const float* __restrict__ dtw_g, const float* __restrict__ dtb_g,
                                                 const float* __restrict__ alog_g, const float* __restrict__ ds_g)
{
    __shared__ float s_u [2][16*96];
    __shared__ float s_xd[2][NPL*16];
    int qb = blockIdx.x, k = blockIdx.y, seg = blockIdx.z, q = qb>>4;
    int c = threadIdx.x;
    int pidx = (q*4+k)*96 + c;
    float dtw[6];
    #pragma unroll
    for (int r=0;r<6;r++) dtw[r]=dtw_g[pidx*6+r];
    float dtb = dtb_g[pidx];
    float Ac[8];
    #pragma unroll
    for (int n=0;n<8;n++) Ac[n] = -__expf(alog_g[pidx*8+n]);
    float Dv = ds_g[pidx];
    const float* u_base  = g_vf + (size_t)qb*LL*96;
    const float* xd_base = g_xdbl + ((size_t)qb*4+k)*NPL*LL;
    float* y_base = g_y + (size_t)qb*LL*96;
    bool rev = (k>=2);
    int kt = k & 1;
    int plane = c>>2, piece = c&3;
    float hs[8];
    #pragma unroll
    for (int n=0;n<8;n++) hs[n]=0.f;
    float sd = 0.f;
    int cg0 = seg*TCH;

    auto load_u = [&](int buf, int sst){
        int a0 = sst/48, b0 = sst%48;
        #pragma unroll
        for (int jj=0;jj<4;jj++){
            int pc = c + 96*jj;
            int off = pc/24, fo = pc%24;
            int row = kt ? ((b0+off)*48 + a0) : (sst+off);
            cpasync16(&s_u[buf][off*96 + fo*4], u_base + (size_t)row*96 + fo*4);
        }
        cpasync16(&s_xd[buf][plane*16 + piece*4], xd_base + (size_t)plane*LL + sst + piece*4);
    };

    {
        int cg = cg0;
        int sst = rev ? (LL - 16*(cg+1)) : 16*cg;
        load_u(0, sst);
        asm volatile("cp.async.commit_group;");
    }
    for (int cs=0; cs<TCH; cs++){
        if (cs<TCH-1){
            int cg = cg0+cs+1;
            int sst = rev ? (LL - 16*(cg+1)) : 16*cg;
            load_u((cs+1) & 1, sst);
            asm volatile("cp.async.commit_group;");
            asm volatile("cp.async.wait_group 1;");
        } else {
            asm volatile("cp.async.wait_group 0;");
        }
        __syncthreads();
        int buf = cs & 1;
        int cg = cg0+cs;
        int sst = rev ? (LL - 16*(cg+1)) : 16*cg;
        int a0 = sst/48, b0 = sst%48;
        const float* xd = &s_xd[buf][0];
        #pragma unroll 4
        for (int j=0;j<16;j++){
            int off = rev ? (15-j) : j;
            float draw = dtb + dtw[0]*xd[0*16+off] + dtw[1]*xd[1*16+off] + dtw[2]*xd[2*16+off]
                             + dtw[3]*xd[3*16+off] + dtw[4]*xd[4*16+off] + dtw[5]*xd[5*16+off];
            float delta = (draw > 15.f) ? draw : __logf(1.f + __expf(draw));
            sd += delta;
            float u = s_u[buf][off*96 + c];
            float du = delta*u;
            float y = Dv*u;
            hs[0] = __expf(delta*Ac[0])*hs[0] + du*xd[( 8)*16+off];  y += hs[0]*xd[(16)*16+off];
            hs[1] = __expf(delta*Ac[1])*hs[1] + du*xd[( 9)*16+off];  y += hs[1]*xd[(17)*16+off];
            hs[2] = __expf(delta*Ac[2])*hs[2] + du*xd[(10)*16+off];  y += hs[2]*xd[(18)*16+off];
            hs[3] = __expf(delta*Ac[3])*hs[3] + du*xd[(11)*16+off];  y += hs[3]*xd[(19)*16+off];
            hs[4] = __expf(delta*Ac[4])*hs[4] + du*xd[(12)*16+off];  y += hs[4]*xd[(20)*16+off];
            hs[5] = __expf(delta*Ac[5])*hs[5] + du*xd[(13)*16+off];  y += hs[5]*xd[(21)*16+off];
            hs[6] = __expf(delta*Ac[6])*hs[6] + du*xd[(14)*16+off];  y += hs[6]*xd[(22)*16+off];
            hs[7] = __expf(delta*Ac[7])*hs[7] + du*xd[(15)*16+off];  y += hs[7]*xd[(23)*16+off];
            int row = kt ? ((b0+off)*48 + a0) : (sst+off);
            atomicAdd(&y_base[(size_t)row*96 + c], y);
        }
        __syncthreads();
    }
    size_t sidx = ((((size_t)qb*4+k)*NSEG+seg)*96 + c);
    g_sd[sidx] = sd;
    #pragma unroll
    for (int n=0;n<8;n++) g_hfin[sidx*8+n] = hs[n];
}

// =============== Scan prefix ===============
__global__ __launch_bounds__(96) void k_scan_prefix(const float* __restrict__ alog_g)
{
    int qb = blockIdx.x, k = blockIdx.y, q = qb>>4;
    int c = threadIdx.x;
    int pidx = (q*4+k)*96 + c;
    float Ac[8];
    #pragma unroll
    for (int n=0;n<8;n++) Ac[n] = -__expf(alog_g[pidx*8+n]);
    float h[8];
    #pragma unroll
    for (int n=0;n<8;n++) h[n]=0.f;
    for (int s=0; s<NSEG; s++){
        size_t sidx = ((((size_t)qb*4+k)*NSEG+s)*96 + c);
        #pragma unroll
        for (int n=0;n<8;n++) g_hin[sidx*8+n] = h[n];
        float sd = g_sd[sidx];
        #pragma unroll
        for (int n=0;n<8;n++) h[n] = __expf(Ac[n]*sd)*h[n] + g_hfin[sidx*8+n];
    }
}

// =============== Scan pass C: carry-in corrections ===============
__global__ __launch_bounds__(96) void k_scan_fix(const float* __restrict__ dtw_g, const float* __restrict__ dtb_g,
                                                 const float* __restrict__ alog_g)
{
    __shared__ float s_xd[2][NPL*16];
    int qb = blockIdx.x, k = blockIdx.y, seg = blockIdx.z+1, q = qb>>4;
    int c = threadIdx.x;
    int pidx = (q*4+k)*96 + c;
    float dtw[6];
    #pragma unroll
    for (int r=0;r<6;r++) dtw[r]=dtw_g[pidx*6+r];
    float dtb = dtb_g[pidx];
    float Ac[8];
    #pragma unroll
    for (int n=0;n<8;n++) Ac[n] = -__expf(alog_g[pidx*8+n]);
    float hin[8];
    {
        size_t sidx = ((((size_t)qb*4+k)*NSEG+seg)*96 + c);
        #pragma unroll
        for (int n=0;n<8;n++) hin[n] = g_hin[sidx*8+n];
    }
    const float* xd_base = g_xdbl + ((size_t)qb*4+k)*NPL*LL;
    float* y_base = g_y + (size_t)qb*LL*96;
    bool rev = (k>=2);
    int kt = k & 1;
    int plane = c>>2, piece = c&3;
    float cum = 0.f;
    int cg0 = seg*TCH;

    auto load_xd = [&](int buf, int sst){
        cpasync16(&s_xd[buf][plane*16 + piece*4], xd_base + (size_t)plane*LL + sst + piece*4);
    };
    {
        int cg = cg0;
        int sst = rev ? (LL - 16*(cg+1)) : 16*cg;
        load_xd(0, sst);
        asm volatile("cp.async.commit_group;");
    }
    for (int cs=0; cs<TCH; cs++){
        if (cs<TCH-1){
            int cg = cg0+cs+1;
            int sst = rev ? (LL - 16*(cg+1)) : 16*cg;
            load_xd((cs+1) & 1, sst);
            asm volatile("cp.async.commit_group;");
            asm volatile("cp.async.wait_group 1;");
        } else {
            asm volatile("cp.async.wait_group 0;");
        }
        __syncthreads();
        int buf = cs & 1;
        int cg = cg0+cs;
        int sst = rev ? (LL - 16*(cg+1)) : 16*cg;
        int a0 = sst/48, b0 = sst%48;
        const float* xd = &s_xd[buf][0];
        #pragma unroll 4
        for (int j=0;j<16;j++){
            int off = rev ? (15-j) : j;
            float draw = dtb + dtw[0]*xd[0*16+off] + dtw[1]*xd[1*16+off] + dtw[2]*xd[2*16+off]
                             + dtw[3]*xd[3*16+off] + dtw[4]*xd[4*16+off] + dtw[5]*xd[5*16+off];
            float delta = (draw > 15.f) ? draw : __logf(1.f + __expf(draw));
            cum += delta;
            float y = 0.f;
            y += xd[(16)*16+off] * (__expf(cum*Ac[0])*hin[0]);
            y += xd[(17)*16+off] * (__expf(cum*Ac[1])*hin[1]);
            y += xd[(18)*16+off] * (__expf(cum*Ac[2])*hin[2]);
            y += xd[(19)*16+off] * (__expf(cum*Ac[3])*hin[3]);
            y += xd[(20)*16+off] * (__expf(cum*Ac[4])*hin[4]);
            y += xd[(21)*16+off] * (__expf(cum*Ac[5])*hin[5]);
            y += xd[(22)*16+off] * (__expf(cum*Ac[6])*hin[6]);
            y += xd[(23)*16+off] * (__expf(cum*Ac[7])*hin[7]);
            int row = kt ? ((b0+off)*48 + a0) : (sst+off);
            atomicAdd(&y_base[(size_t)row*96 + c], y);
        }
        __syncthreads();
    }
}

// =============== K4: ssln LN + p2n LN + a*z + ysum ===============
__global__ __launch_bounds__(96) void k4_comb(const float* __restrict__ g1g, const float* __restrict__ b1g,
                                              const float* __restrict__ g2g, const float* __restrict__ b2g,
                                              const int* __restrict__ bidx)
{
    __shared__ float T[48*97];
    __shared__ float mu1[48], rs1[48], mu2[48], rs2[48];
    __shared__ float G1[96], B1[96], G2[96], B2[96];
    int qb = blockIdx.x, q = qb>>4, hr = blockIdx.y, tid = threadIdx.x;
    bool even = ((bidx[0] & 1) == 0);
    G1[tid]=g1g[q*96+tid]; B1[tid]=b1g[q*96+tid];
    G2[tid]=g2g[q*96+tid]; B2[tid]=b2g[q*96+tid];
    const float* yb = g_y + (size_t)qb*LL*96;
    for (int i=tid; i<48*96; i+=96){
        int w=i/96, c=i%96;
        int pf = even ? (w*48+hr) : ((47-hr)*48+(47-w));
        T[w*97+c] = yb[(size_t)pf*96+c];
    }
    __syncthreads();
    {
        int p = tid>>1, half = tid&1;
        float s=0.f, ss=0.f;
        const float* row = &T[p*97 + half*48];
        #pragma unroll 8
        for (int c=0;c<48;c++){ float v=row[c]; s+=v; ss+=v*v; }
        s  += __shfl_xor_sync(0xffffffffu, s, 1);
        ss += __shfl_xor_sync(0xffffffffu, ss, 1);
        if (half==0){
            float m = s*(1.f/96.f);
            mu1[p]=m; rs1[p]=rsqrtf(ss*(1.f/96.f)-m*m+1e-6f);
        }
    }
    __syncthreads();
    {
        int p = tid>>1, half = tid&1;
        float m1=mu1[p], r1=rs1[p];
        float s=0.f, ss=0.f;
        const float* row = &T[p*97 + half*48];
        const float* gg = &G1[half*48];
        const float* bb = &B1[half*48];
        #pragma unroll 8
        for (int c=0;c<48;c++){ float t=(row[c]-m1)*r1*gg[c]+bb[c]; s+=t; ss+=t*t; }
        s  += __shfl_xor_sync(0xffffffffu, s, 1);
        ss += __shfl_xor_sync(0xffffffffu, ss, 1);
        if (half==0){
            float m = s*(1.f/96.f);
            mu2[p]=m; rs2[p]=rsqrtf(ss*(1.f/96.f)-m*m+1e-6f);
        }
    }
    __syncthreads();
    {
        int c = tid;
        float g1=G1[c], b1=B1[c], g2=G2[c], b2=B2[c];
        float ysum=0.f;
        const float* ab = g_a  + ((size_t)qb*LL + hr*48)*96;
        float*       yo = g_yo + ((size_t)qb*LL + hr*48)*96;
        for (int w=0; w<48; w++){
            float o = T[w*97+c];
            float t  = (o-mu1[w])*rs1[w]*g1 + b1;
            float z2 = (t-mu2[w])*rs2[w]*g2 + b2;
            float a = ab[(size_t)w*96 + c];
            float y = a*z2;
            ysum += y;
            yo[(size_t)w*96 + c] = y;
        }
        atomicAdd(&g_ysum[qb*96+c], ysum);
    }
}

// =============== K5: channel attention ===============
__global__ __launch_bounds__(96) void k5_att(const float* __restrict__ w1, const float* __restrict__ b1,
                                             const float* __restrict__ w2, const float* __restrict__ b2)
{
    __shared__ float sv[96], tv[12];
    int qb = blockIdx.x, q = qb>>4, c = threadIdx.x;
    sv[c] = g_ysum[qb*96+c] * (1.f/2304.f);
    __syncthreads();
    if (c<12){
        float acc = b1[q*12+c];
        #pragma unroll 8
        for (int cc=0; cc<96; cc++) acc += w1[(q*12+c)*96+cc]*sv[cc];
        tv[c] = siluf(acc);
    }
    __syncthreads();
    float acc = b2[q*96+c];
    #pragma unroll
    for (int r=0;r<12;r++) acc += w2[(q*96+c)*12+r]*tv[r];
    g_att[qb*96+c] = 1.f/(1.f+__expf(-acc));
}

// =============== K6: residual + att + transpose to NCHW ===============
__global__ __launch_bounds__(256) void k6_fin(const float* __restrict__ x, float* __restrict__ out)
{
    __shared__ float tile[96*49];
    __shared__ float atts[96];
    int qb = blockIdx.x, q = qb>>4, bb = qb&15, hr = blockIdx.y;
    int qh=(q>>1)*48, qw=(q&1)*48;
    const float* src = g_yo + ((size_t)qb*LL + hr*48)*96;
    for (int i=threadIdx.x; i<48*96; i+=256){
        int w=i/96, c=i%96;
        tile[c*49+w] = src[i];
    }
    for (int i=threadIdx.x; i<96; i+=256) atts[i]=g_att[qb*96+i];
    __syncthreads();
    for (int i=threadIdx.x; i<96*48; i+=256){
        int c=i/48, w=i%48;
        size_t oi = ((size_t)(bb*96+c)*96 + qh+hr)*96 + qw + w;
        out[oi] = x[oi] + tile[c*49+w]*atts[c];
    }
}

// ================================================================
extern "C" void kernel_launch(void* const* d_in, const int* in_sizes, int n_in,
                              void* d_out, int out_size)
{
    const float* x    = (const float*)d_in[0];
    const float* ln_g = (const float*)d_in[1];
    const float* ln_b = (const float*)d_in[2];
    const float* p1w  = (const float*)d_in[3];
    const float* p1b  = (const float*)d_in[4];
    const float* p2w  = (const float*)d_in[5];
    const float* p2b  = (const float*)d_in[6];
    const float* dww  = (const float*)d_in[7];
    const float* dwb  = (const float*)d_in[8];
    const float* xprj = (const float*)d_in[9];
    const float* dtw  = (const float*)d_in[10];
    const float* dtb  = (const float*)d_in[11];
    const float* alog = (const float*)d_in[12];
    const float* dsv  = (const float*)d_in[13];
    const float* ssg  = (const float*)d_in[14];
    const float* ssb  = (const float*)d_in[15];
    const float* png  = (const float*)d_in[16];
    const float* pnb  = (const float*)d_in[17];
    const float* cw1  = (const float*)d_in[18];
    const float* cb1  = (const float*)d_in[19];
    const float* cw2  = (const float*)d_in[20];
    const float* cb2  = (const float*)d_in[21];
    const int*   bidx = (const int*)  d_in[22];
    float* out = (float*)d_out;

    const int smem_k1 = (96*X1S + 96*W1S)*4;
    const int smem_k2 = 3*48*96*4;
    const int smem_k3 = (96*K3XS + 96*K3WS)*4;
    cudaFuncSetAttribute(k1_gemm, cudaFuncAttributeMaxDynamicSharedMemorySize, smem_k1);
    cudaFuncSetAttribute(k2_dw,   cudaFuncAttributeMaxDynamicSharedMemorySize, smem_k2);
    cudaFuncSetAttribute(k3_proj, cudaFuncAttributeMaxDynamicSharedMemorySize, smem_k3);

    k1_gemm<<<dim3(576,4), 128, smem_k1>>>(x, ln_g, ln_b, p1w, p1b, p2w, p2b);
    k2_dw  <<<dim3(64,48), 256, smem_k2>>>(dww, dwb, bidx);
    k3_proj<<<dim3(288,2,4), 128, smem_k3>>>(xprj);
    k_scan_seg   <<<dim3(64,4,NSEG), 96>>>(dtw, dtb, alog, dsv);
    k_scan_prefix<<<dim3(64,4), 96>>>(alog);
    k_scan_fix   <<<dim3(64,4,NSEG-1), 96>>>(dtw, dtb, alog);
    k4_comb<<<dim3(64,48), 96>>>(ssg, ssb, png, pnb, bidx);
    k5_att <<<64, 96>>>(cw1, cb1, cw2, cb2);
    k6_fin <<<dim3(64,48), 256>>>(x, out);
}

// round 11
// speedup vs baseline: 1.0744x; 1.0744x over previous
#include <cuda_runtime.h>
#include <cuda_bf16.h>
#include <cstdint>

#define CC   96
#define LL   2304
#define NBQ  64
#define PXQ  36864
#define NPL  24
#define NSEG 8
#define TCH  18

// ---------------- static scratch ----------------
__device__ float g_a   [NBQ*LL*CC];
__device__ float g_zin [NBQ*LL*CC];
__device__ float g_vf  [NBQ*LL*CC];
__device__ float g_xdbl[NBQ*4*NPL*LL];
__device__ float g_y   [NBQ*LL*CC];
__device__ float g_yo  [NBQ*LL*CC];
__device__ float g_ysum[NBQ*CC];
__device__ float g_att [NBQ*CC];
__device__ float g_sd  [NBQ*4*NSEG*CC];
__device__ float g_hfin[NBQ*4*NSEG*CC*8];
__device__ float g_hin [NBQ*4*NSEG*CC*8];

__device__ __forceinline__ float siluf(float v){ return v * (1.f/(1.f+__expf(-v))); }

__device__ __forceinline__ void fma2(unsigned long long &acc, unsigned long long a, unsigned long long b){
    asm("fma.rn.f32x2 %0,%1,%2,%0;" : "+l"(acc) : "l"(a), "l"(b));
}
__device__ __forceinline__ unsigned long long pack2(float v){
    unsigned long long r; asm("mov.b64 %0,{%1,%1};" : "=l"(r) : "f"(v)); return r;
}
__device__ __forceinline__ float2 unpack2(unsigned long long v){
    float2 r; asm("mov.b64 {%0,%1},%2;" : "=f"(r.x), "=f"(r.y) : "l"(v)); return r;
}
__device__ __forceinline__ void cpasync16(void* dst, const void* src){
    unsigned d = (unsigned)__cvta_generic_to_shared(dst);
    asm volatile("cp.async.ca.shared.global [%0],[%1],16;" :: "r"(d), "l"(src));
}

// =============== K1: LN + BOTH 1x1 convs fused (round-9 config) ===============
#define X1S 68
#define W1S 198
__global__ __launch_bounds__(256,2) void k1_gemm(const float* __restrict__ x,
                                                 const float* __restrict__ lg, const float* __restrict__ lb,
                                                 const float* __restrict__ p1w, const float* __restrict__ p1b,
                                                 const float* __restrict__ p2w, const float* __restrict__ p2b)
{
    extern __shared__ float sm[];
    float* Xs = sm;
    float* Ws = sm + 96*X1S;
    __shared__ float mu[64], rs[64];
    __shared__ float b0s[96], b1s[96];
    int q = blockIdx.y, P0 = blockIdx.x*64;
    int bb = P0 / LL, l0 = P0 % LL;
    int qh=(q>>1)*48, qw=(q&1)*48;
    const float* xb = x + (size_t)bb*884736 + (size_t)qh*96 + qw;
    for (int i=threadIdx.x; i<96*64; i+=256){
        int c=i>>6, p=i&63;
        int l=l0+p, h=l/48, w=l%48;
        Xs[c*X1S+p] = xb[(size_t)c*9216 + h*96 + w];
    }
    const float* W0 = p1w + (size_t)q*9216;
    const float* W1 = p2w + (size_t)q*9216;
    for (int i=threadIdx.x; i<9216; i+=256){
        int d=i/96, c=i%96;
        Ws[c*W1S+d]    = W0[i];
        Ws[c*W1S+96+d] = W1[i];
    }
    for (int i=threadIdx.x; i<96; i+=256){ b0s[i]=p1b[q*96+i]; b1s[i]=p2b[q*96+i]; }
    __syncthreads();
    {
        int px = threadIdx.x>>2, part = threadIdx.x&3;
        float s=0.f, ss=0.f;
        const float* col = Xs + px;
        #pragma unroll 8
        for (int cc=part*24; cc<part*24+24; cc++){ float v=col[cc*X1S]; s+=v; ss+=v*v; }
        s  += __shfl_xor_sync(0xffffffffu, s, 1);
        ss += __shfl_xor_sync(0xffffffffu, ss, 1);
        s  += __shfl_xor_sync(0xffffffffu, s, 2);
        ss += __shfl_xor_sync(0xffffffffu, ss, 2);
        if (part==0){
            float m = s*(1.f/96.f);
            mu[px]=m; rs[px]=rsqrtf(ss*(1.f/96.f)-m*m+1e-6f);
        }
    }
    __syncthreads();
    for (int i=threadIdx.x; i<96*64; i+=256){
        int c=i>>6, p=i&63;
        Xs[c*X1S+p] = (Xs[c*X1S+p]-mu[p])*rs[p]*lg[q*96+c] + lb[q*96+c];
    }
    __syncthreads();
    int tp = threadIdx.x & 15, tc = threadIdx.x >> 4;
    unsigned long long acc[6][4];
    #pragma unroll
    for (int j=0;j<6;j++){ acc[j][0]=0ull; acc[j][1]=0ull; acc[j][2]=0ull; acc[j][3]=0ull; }
    const float* xbq = Xs + 4*tp;
    const float* wbq = Ws + 12*tc;
    #pragma unroll 2
    for (int k=0;k<96;k++){
        float4 xv = *(const float4*)(xbq + k*X1S);
        unsigned long long xd0 = pack2(xv.x), xd1 = pack2(xv.y),
                           xd2 = pack2(xv.z), xd3 = pack2(xv.w);
        const unsigned long long* wp = (const unsigned long long*)(wbq + k*W1S);
        #pragma unroll
        for (int j=0;j<6;j++){
            unsigned long long wv = wp[j];
            fma2(acc[j][0], wv, xd0);
            fma2(acc[j][1], wv, xd1);
            fma2(acc[j][2], wv, xd2);
            fma2(acc[j][3], wv, xd3);
        }
    }
    __syncthreads();
    float* sout = sm;                 // [64][100]
    if (tc < 8){
        #pragma unroll
        for (int j=0;j<6;j++){
            int oc = 12*tc + 2*j;
            #pragma unroll
            for (int i=0;i<4;i++){
                float2 v = unpack2(acc[j][i]);
                sout[(size_t)(4*tp+i)*100 + oc    ] = v.x;
                sout[(size_t)(4*tp+i)*100 + oc + 1] = v.y;
            }
        }
    }
    __syncthreads();
    {
        float* dst = g_a + ((size_t)q*PXQ + P0)*96;
        for (int i=threadIdx.x; i<64*96; i+=256){
            int p=i/96, oc=i%96;
            dst[i] = siluf(sout[p*100+oc] + b0s[oc]);
        }
    }
    __syncthreads();
    if (tc >= 8){
        #pragma unroll
        for (int j=0;j<6;j++){
            int oc = 12*(tc-8) + 2*j;
            #pragma unroll
            for (int i=0;i<4;i++){
                float2 v = unpack2(acc[j][i]);
                sout[(size_t)(4*tp+i)*100 + oc    ] = v.x;
                sout[(size_t)(4*tp+i)*100 + oc + 1] = v.y;
            }
        }
    }
    __syncthreads();
    {
        float* dst = g_zin + ((size_t)q*PXQ + P0)*96;
        for (int i=threadIdx.x; i<64*96; i+=256){
            int p=i/96, oc=i%96;
            dst[i] = sout[p*100+oc] + b1s[oc];
        }
    }
}

// =============== K2: depthwise 3x3 + bias + silu + pre-transform; zeros g_y ===============
__global__ __launch_bounds__(256) void k2_dw(const float* __restrict__ dww, const float* __restrict__ dwb,
                                             const int* __restrict__ bidx)
{
    extern __shared__ float rows[];
    __shared__ float wsm[96*9];
    __shared__ float bsm[96];
    int qb = blockIdx.x, q = qb>>4, hr = blockIdx.y;
    if (blockIdx.x==0 && blockIdx.y==0)
        for (int i=threadIdx.x; i<NBQ*CC; i+=256) g_ysum[i]=0.f;
    {
        float* yz = g_y + ((size_t)qb*LL + hr*48)*96;
        for (int i=threadIdx.x; i<48*96; i+=256) yz[i]=0.f;
    }
    for (int i=threadIdx.x; i<96*9; i+=256) wsm[i]=dww[q*96*9 + i];
    for (int i=threadIdx.x; i<96;   i+=256) bsm[i]=dwb[q*96 + i];
    for (int dy=0; dy<3; dy++){
        int hh = hr-1+dy;
        if (hh>=0 && hh<48){
            const float* src = g_zin + ((size_t)qb*LL + hh*48)*96;
            for (int i=threadIdx.x; i<48*96; i+=256) rows[dy*4608+i]=src[i];
        } else {
            for (int i=threadIdx.x; i<48*96; i+=256) rows[dy*4608+i]=0.f;
        }
    }
    __syncthreads();
    bool even = ((bidx[0] & 1) == 0);
    for (int i=threadIdx.x; i<48*96; i+=256){
        int w=i/96, c=i%96;
        float acc = bsm[c];
        #pragma unroll
        for (int dy=0; dy<3; dy++){
            #pragma unroll
            for (int dx=0; dx<3; dx++){
                int ww = w+dx-1;
                if (ww>=0 && ww<48) acc += wsm[c*9+dy*3+dx]*rows[dy*4608 + ww*96 + c];
            }
        }
        float z = siluf(acc);
        int pf = even ? (w*48+hr) : ((47-hr)*48+(47-w));
        g_vf[((size_t)qb*LL + pf)*96 + c] = z;
    }
}

// =============== K3: x-projection GEMM (round-9 config) ===============
#define K3XS 132
#define K3WS 50
__global__ __launch_bounds__(256,3) void k3_proj(const float* __restrict__ xprojw)
{
    extern __shared__ float sm[];
    float* Xs = sm;
    float* Ws = sm + 96*K3XS;
    int q = blockIdx.z, src = blockIdx.y, P0 = blockIdx.x*128;
    int b_img = P0 / LL;
    int l0 = P0 % LL;
    const float* vbase = g_vf + (size_t)(q*16 + b_img)*LL*96;
    for (int i=threadIdx.x; i<128*96; i+=256){
        int p=i/96, c=i%96;
        int l = l0 + p;
        int row = src ? ((l%48)*48 + l/48) : l;
        Xs[c*K3XS+p] = vbase[(size_t)row*96 + c];
    }
    for (int i=threadIdx.x; i<48*96; i+=256){
        int oc=i/96, kk=i%96;
        float v=0.f;
        if (oc<44){
            int k = (oc<22)? src : src+2;
            int d = (oc<22)? oc : oc-22;
            v = xprojw[(((size_t)q*4 + k)*22 + d)*96 + kk];
        }
        Ws[kk*K3WS+oc]=v;
    }
    __syncthreads();
    int tp = threadIdx.x & 31, tc = threadIdx.x >> 5;
    unsigned long long acc[3][4];
    #pragma unroll
    for (int j=0;j<3;j++){ acc[j][0]=0ull; acc[j][1]=0ull; acc[j][2]=0ull; acc[j][3]=0ull; }
    const float* xbq = Xs + 4*tp;
    const float* wbq = Ws + 6*tc;
    #pragma unroll 4
    for (int k=0;k<96;k++){
        float4 xv = *(const float4*)(xbq + k*K3XS);
        unsigned long long xd0 = pack2(xv.x), xd1 = pack2(xv.y),
                           xd2 = pack2(xv.z), xd3 = pack2(xv.w);
        const unsigned long long* wp = (const unsigned long long*)(wbq + k*K3WS);
        #pragma unroll
        for (int j=0;j<3;j++){
            unsigned long long wv = wp[j];
            fma2(acc[j][0], wv, xd0);
            fma2(acc[j][1], wv, xd1);
            fma2(acc[j][2], wv, xd2);
            fma2(acc[j][3], wv, xd3);
        }
    }
    int qb = q*16 + b_img;
    int lw = l0 + 4*tp;
    #pragma unroll
    for (int j=0;j<3;j++){
        float2 v0 = unpack2(acc[j][0]);
        float2 v1 = unpack2(acc[j][1]);
        float2 v2 = unpack2(acc[j][2]);
        float2 v3 = unpack2(acc[j][3]);
        #pragma unroll
        for (int h=0; h<2; h++){
            int oc = 6*tc + 2*j + h;
            if (oc>=44) continue;
            int kdir = (oc<22)? src : src+2;
            int d    = (oc<22)? oc : oc-22;
            int plane= (d<6)? d : d+2;
            float* dst = g_xdbl + (((size_t)qb*4 + kdir)*NPL + plane)*LL + lw;
            *(float4*)dst = h ? make_float4(v0.y,v1.y,v2.y,v3.y)
                              : make_float4(v0.x,v1.x,v2.x,v3.x);
        }
    }
}

// =============== Scan pass A: segmented local scan (h0=0) ===============
__global__ __launch_bounds__(96) void k_scan_seg(const float* __restrict__ dtw_g, const float* __restrict__ dtb_g,
                                                 const float* __restrict__ alog_g, const float* __restrict__ ds_g)
{
    __shared__ float s_u [2][16*96];
    __shared__ float s_xd[2][NPL*16];
    int qb = blockIdx.x, k = blockIdx.y, seg = blockIdx.z, q = qb>>4;
    int c = threadIdx.x;
    int pidx = (q*4+k)*96 + c;
    float dtw[6];
    #pragma unroll
    for (int r=0;r<6;r++) dtw[r]=dtw_g[pidx*6+r];
    float dtb = dtb_g[pidx];
    float Ac[8];
    #pragma unroll
    for (int n=0;n<8;n++) Ac[n] = -__expf(alog_g[pidx*8+n]);
    float Dv = ds_g[pidx];
    const float* u_base  = g_vf + (size_t)qb*LL*96;
    const float* xd_base = g_xdbl + ((size_t)qb*4+k)*NPL*LL;
    float* y_base = g_y + (size_t)qb*LL*96;
    bool rev = (k>=2);
    int kt = k & 1;
    int plane = c>>2, piece = c&3;
    bool pneed = (plane<6) || (plane>=8);       // skip pad planes 6,7
    float hs[8];
    #pragma unroll
    for (int n=0;n<8;n++) hs[n]=0.f;
    float sd = 0.f;
    int cg0 = seg*TCH;

    auto load_u = [&](int buf, int sst){
        int a0 = sst/48, b0 = sst%48;
        #pragma unroll
        for (int jj=0;jj<4;jj++){
            int pc = c + 96*jj;
            int off = pc/24, fo = pc%24;
            int row = kt ? ((b0+off)*48 + a0) : (sst+off);
            cpasync16(&s_u[buf][off*96 + fo*4], u_base + (size_t)row*96 + fo*4);
        }
        if (pneed)
            cpasync16(&s_xd[buf][plane*16 + piece*4], xd_base + (size_t)plane*LL + sst + piece*4);
    };

    {
        int cg = cg0;
        int sst = rev ? (LL - 16*(cg+1)) : 16*cg;
        load_u(0, sst);
        asm volatile("cp.async.commit_group;");
    }
    for (int cs=0; cs<TCH; cs++){
        if (cs<TCH-1){
            int cg = cg0+cs+1;
            int sst = rev ? (LL - 16*(cg+1)) : 16*cg;
            load_u((cs+1) & 1, sst);
            asm volatile("cp.async.commit_group;");
            asm volatile("cp.async.wait_group 1;");
        } else {
            asm volatile("cp.async.wait_group 0;");
        }
        __syncthreads();
        int buf = cs & 1;
        int cg = cg0+cs;
        int sst = rev ? (LL - 16*(cg+1)) : 16*cg;
        int a0 = sst/48, b0 = sst%48;
        const float* xd = &s_xd[buf][0];
        #pragma unroll 4
        for (int j=0;j<16;j++){
            int off = rev ? (15-j) : j;
            float draw = dtb + dtw[0]*xd[0*16+off] + dtw[1]*xd[1*16+off] + dtw[2]*xd[2*16+off]
                             + dtw[3]*xd[3*16+off] + dtw[4]*xd[4*16+off] + dtw[5]*xd[5*16+off];
            float delta = (draw > 15.f) ? draw : __logf(1.f + __expf(draw));
            sd += delta;
            float u = s_u[buf][off*96 + c];
            float du = delta*u;
            float y = Dv*u;
            hs[0] = __expf(delta*Ac[0])*hs[0] + du*xd[( 8)*16+off];  y += hs[0]*xd[(16)*16+off];
            hs[1] = __expf(delta*Ac[1])*hs[1] + du*xd[( 9)*16+off];  y += hs[1]*xd[(17)*16+off];
            hs[2] = __expf(delta*Ac[2])*hs[2] + du*xd[(10)*16+off];  y += hs[2]*xd[(18)*16+off];
            hs[3] = __expf(delta*Ac[3])*hs[3] + du*xd[(11)*16+off];  y += hs[3]*xd[(19)*16+off];
            hs[4] = __expf(delta*Ac[4])*hs[4] + du*xd[(12)*16+off];  y += hs[4]*xd[(20)*16+off];
            hs[5] = __expf(delta*Ac[5])*hs[5] + du*xd[(13)*16+off];  y += hs[5]*xd[(21)*16+off];
            hs[6] = __expf(delta*Ac[6])*hs[6] + du*xd[(14)*16+off];  y += hs[6]*xd[(22)*16+off];
            hs[7] = __expf(delta*Ac[7])*hs[7] + du*xd[(15)*16+off];  y += hs[7]*xd[(23)*16+off];
            int row = kt ? ((b0+off)*48 + a0) : (sst+off);
            atomicAdd(&y_base[(size_t)row*96 + c], y);
        }
        __syncthreads();
    }
    size_t sidx = ((((size_t)qb*4+k)*NSEG+seg)*96 + c);
    g_sd[sidx] = sd;
    #pragma unroll
    for (int n=0;n<8;n++) g_hfin[sidx*8+n] = hs[n];
}

// =============== Scan prefix ===============
__global__ __launch_bounds__(96) void k_scan_prefix(const float* __restrict__ alog_g)
{
    int qb = blockIdx.x, k = blockIdx.y, q = qb>>4;
    int c = threadIdx.x;
    int pidx = (q*4+k)*96 + c;
    float Ac[8];
    #pragma unroll
    for (int n=0;n<8;n++) Ac[n] = -__expf(alog_g[pidx*8+n]);
    float h[8];
    #pragma unroll
    for (int n=0;n<8;n++) h[n]=0.f;
    for (int s=0; s<NSEG; s++){
        size_t sidx = ((((size_t)qb*4+k)*NSEG+s)*96 + c);
        #pragma unroll
        for (int n=0;n<8;n++) g_hin[sidx*8+n] = h[n];
        float sd = g_sd[sidx];
        #pragma unroll
        for (int n=0;n<8;n++) h[n] = __expf(Ac[n]*sd)*h[n] + g_hfin[sidx*8+n];
    }
}

// =============== Scan pass C: carry-in corrections ===============
__global__ __launch_bounds__(96) void k_scan_fix(const float* __restrict__ dtw_g, const float* __restrict__ dtb_g,
                                                 const float* __restrict__ alog_g)
{
    __shared__ float s_xd[2][NPL*16];
    int qb = blockIdx.x, k = blockIdx.y, seg = blockIdx.z+1, q = qb>>4;
    int c = threadIdx.x;
    int pidx = (q*4+k)*96 + c;
    float dtw[6];
    #pragma unroll
    for (int r=0;r<6;r++) dtw[r]=dtw_g[pidx*6+r];
    float dtb = dtb_g[pidx];
    float Ac[8];
    #pragma unroll
    for (int n=0;n<8;n++) Ac[n] = -__expf(alog_g[pidx*8+n]);
    float hin[8];
    {
        size_t sidx = ((((size_t)qb*4+k)*NSEG+seg)*96 + c);
        #pragma unroll
        for (int n=0;n<8;n++) hin[n] = g_hin[sidx*8+n];
    }
    const float* xd_base = g_xdbl + ((size_t)qb*4+k)*NPL*LL;
    float* y_base = g_y + (size_t)qb*LL*96;
    bool rev = (k>=2);
    int kt = k & 1;
    int plane = c>>2, piece = c&3;
    bool pneed = (plane<6) || (plane>=16);      // only dts + C planes
    float cum = 0.f;
    int cg0 = seg*TCH;

    auto load_xd = [&](int buf, int sst){
        if (pneed)
            cpasync16(&s_xd[buf][plane*16 + piece*4], xd_base + (size_t)plane*LL + sst + piece*4);
    };
    {
        int cg = cg0;
        int sst = rev ? (LL - 16*(cg+1)) : 16*cg;
        load_xd(0, sst);
        asm volatile("cp.async.commit_group;");
    }
    for (int cs=0; cs<TCH; cs++){
        if (cs<TCH-1){
            int cg = cg0+cs+1;
            int sst = rev ? (LL - 16*(cg+1)) : 16*cg;
            load_xd((cs+1) & 1, sst);
            asm volatile("cp.async.commit_group;");
            asm volatile("cp.async.wait_group 1;");
        } else {
            asm volatile("cp.async.wait_group 0;");
        }
        __syncthreads();
        int buf = cs & 1;
        int cg = cg0+cs;
        int sst = rev ? (LL - 16*(cg+1)) : 16*cg;
        int a0 = sst/48, b0 = sst%48;
        const float* xd = &s_xd[buf][0];
        #pragma unroll 4
        for (int j=0;j<16;j++){
            int off = rev ? (15-j) : j;
            float draw = dtb + dtw[0]*xd[0*16+off] + dtw[1]*xd[1*16+off] + dtw[2]*xd[2*16+off]
                             + dtw[3]*xd[3*16+off] + dtw[4]*xd[4*16+off] + dtw[5]*xd[5*16+off];
            float delta = (draw > 15.f) ? draw : __logf(1.f + __expf(draw));
            cum += delta;
            float y = 0.f;
            y += xd[(16)*16+off] * (__expf(cum*Ac[0])*hin[0]);
            y += xd[(17)*16+off] * (__expf(cum*Ac[1])*hin[1]);
            y += xd[(18)*16+off] * (__expf(cum*Ac[2])*hin[2]);
            y += xd[(19)*16+off] * (__expf(cum*Ac[3])*hin[3]);
            y += xd[(20)*16+off] * (__expf(cum*Ac[4])*hin[4]);
            y += xd[(21)*16+off] * (__expf(cum*Ac[5])*hin[5]);
            y += xd[(22)*16+off] * (__expf(cum*Ac[6])*hin[6]);
            y += xd[(23)*16+off] * (__expf(cum*Ac[7])*hin[7]);
            int row = kt ? ((b0+off)*48 + a0) : (sst+off);
            atomicAdd(&y_base[(size_t)row*96 + c], y);
        }
        __syncthreads();
    }
}

// =============== K4: ssln LN + p2n LN + a*z + ysum ===============
__global__ __launch_bounds__(96) void k4_comb(const float* __restrict__ g1g, const float* __restrict__ b1g,
                                              const float* __restrict__ g2g, const float* __restrict__ b2g,
                                              const int* __restrict__ bidx)
{
    __shared__ float T[48*97];
    __shared__ float mu1[48], rs1[48], mu2[48], rs2[48];
    __shared__ float G1[96], B1[96], G2[96], B2[96];
    int qb = blockIdx.x, q = qb>>4, hr = blockIdx.y, tid = threadIdx.x;
    bool even = ((bidx[0] & 1) == 0);
    G1[tid]=g1g[q*96+tid]; B1[tid]=b1g[q*96+tid];
    G2[tid]=g2g[q*96+tid]; B2[tid]=b2g[q*96+tid];
    const float* yb = g_y + (size_t)qb*LL*96;
    for (int i=tid; i<48*96; i+=96){
        int w=i/96, c=i%96;
        int pf = even ? (w*48+hr) : ((47-hr)*48+(47-w));
        T[w*97+c] = yb[(size_t)pf*96+c];
    }
    __syncthreads();
    {
        int p = tid>>1, half = tid&1;
        float s=0.f, ss=0.f;
        const float* row = &T[p*97 + half*48];
        #pragma unroll 8
        for (int c=0;c<48;c++){ float v=row[c]; s+=v; ss+=v*v; }
        s  += __shfl_xor_sync(0xffffffffu, s, 1);
        ss += __shfl_xor_sync(0xffffffffu, ss, 1);
        if (half==0){
            float m = s*(1.f/96.f);
            mu1[p]=m; rs1[p]=rsqrtf(ss*(1.f/96.f)-m*m+1e-6f);
        }
    }
    __syncthreads();
    {
        int p = tid>>1, half = tid&1;
        float m1=mu1[p], r1=rs1[p];
        float s=0.f, ss=0.f;
        const float* row = &T[p*97 + half*48];
        const float* gg = &G1[half*48];
        const float* bb = &B1[half*48];
        #pragma unroll 8
        for (int c=0;c<48;c++){ float t=(row[c]-m1)*r1*gg[c]+bb[c]; s+=t; ss+=t*t; }
        s  += __shfl_xor_sync(0xffffffffu, s, 1);
        ss += __shfl_xor_sync(0xffffffffu, ss, 1);
        if (half==0){
            float m = s*(1.f/96.f);
            mu2[p]=m; rs2[p]=rsqrtf(ss*(1.f/96.f)-m*m+1e-6f);
        }
    }
    __syncthreads();
    {
        int c = tid;
        float g1=G1[c], b1=B1[c], g2=G2[c], b2=B2[c];
        float ysum=0.f;
        const float* ab = g_a  + ((size_t)qb*LL + hr*48)*96;
        float*       yo = g_yo + ((size_t)qb*LL + hr*48)*96;
        for (int w=0; w<48; w++){
            float o = T[w*97+c];
            float t  = (o-mu1[w])*rs1[w]*g1 + b1;
            float z2 = (t-mu2[w])*rs2[w]*g2 + b2;
            float a = ab[(size_t)w*96 + c];
            float y = a*z2;
            ysum += y;
            yo[(size_t)w*96 + c] = y;
        }
        atomicAdd(&g_ysum[qb*96+c], ysum);
    }
}

// =============== K5: channel attention ===============
__global__ __launch_bounds__(96) void k5_att(const float* __restrict__ w1, const float* __restrict__ b1,
                                             const float* __restrict__ w2, const float* __restrict__ b2)
{
    __shared__ float sv[96], tv[12];
    int qb = blockIdx.x, q = qb>>4, c = threadIdx.x;
    sv[c] = g_ysum[qb*96+c] * (1.f/2304.f);
    __syncthreads();
    if (c<12){
        float acc = b1[q*12+c];
        #pragma unroll 8
        for (int cc=0; cc<96; cc++) acc += w1[(q*12+c)*96+cc]*sv[cc];
        tv[c] = siluf(acc);
    }
    __syncthreads();
    float acc = b2[q*96+c];
    #pragma unroll
    for (int r=0;r<12;r++) acc += w2[(q*96+c)*12+r]*tv[r];
    g_att[qb*96+c] = 1.f/(1.f+__expf(-acc));
}

// =============== K6: residual + att + transpose to NCHW ===============
__global__ __launch_bounds__(256) void k6_fin(const float* __restrict__ x, float* __restrict__ out)
{
    __shared__ float tile[96*49];
    __shared__ float atts[96];
    int qb = blockIdx.x, q = qb>>4, bb = qb&15, hr = blockIdx.y;
    int qh=(q>>1)*48, qw=(q&1)*48;
    const float* src = g_yo + ((size_t)qb*LL + hr*48)*96;
    for (int i=threadIdx.x; i<48*96; i+=256){
        int w=i/96, c=i%96;
        tile[c*49+w] = src[i];
    }
    for (int i=threadIdx.x; i<96; i+=256) atts[i]=g_att[qb*96+i];
    __syncthreads();
    for (int i=threadIdx.x; i<96*48; i+=256){
        int c=i/48, w=i%48;
        size_t oi = ((size_t)(bb*96+c)*96 + qh+hr)*96 + qw + w;
        out[oi] = x[oi] + tile[c*49+w]*atts[c];
    }
}

// ================================================================
extern "C" void kernel_launch(void* const* d_in, const int* in_sizes, int n_in,
                              void* d_out, int out_size)
{
    const float* x    = (const float*)d_in[0];
    const float* ln_g = (const float*)d_in[1];
    const float* ln_b = (const float*)d_in[2];
    const float* p1w  = (const float*)d_in[3];
    const float* p1b  = (const float*)d_in[4];
    const float* p2w  = (const float*)d_in[5];
    const float* p2b  = (const float*)d_in[6];
    const float* dww  = (const float*)d_in[7];
    const float* dwb  = (const float*)d_in[8];
    const float* xprj = (const float*)d_in[9];
    const float* dtw  = (const float*)d_in[10];
    const float* dtb  = (const float*)d_in[11];
    const float* alog = (const float*)d_in[12];
    const float* dsv  = (const float*)d_in[13];
    const float* ssg  = (const float*)d_in[14];
    const float* ssb  = (const float*)d_in[15];
    const float* png  = (const float*)d_in[16];
    const float* pnb  = (const float*)d_in[17];
    const float* cw1  = (const float*)d_in[18];
    const float* cb1  = (const float*)d_in[19];
    const float* cw2  = (const float*)d_in[20];
    const float* cb2  = (const float*)d_in[21];
    const int*   bidx = (const int*)  d_in[22];
    float* out = (float*)d_out;

    const int smem_k1 = (96*X1S + 96*W1S)*4;
    const int smem_k2 = 3*48*96*4;
    const int smem_k3 = (96*K3XS + 96*K3WS)*4;
    cudaFuncSetAttribute(k1_gemm, cudaFuncAttributeMaxDynamicSharedMemorySize, smem_k1);
    cudaFuncSetAttribute(k2_dw,   cudaFuncAttributeMaxDynamicSharedMemorySize, smem_k2);
    cudaFuncSetAttribute(k3_proj, cudaFuncAttributeMaxDynamicSharedMemorySize, smem_k3);

    k1_gemm<<<dim3(576,4), 256, smem_k1>>>(x, ln_g, ln_b, p1w, p1b, p2w, p2b);
    k2_dw  <<<dim3(64,48), 256, smem_k2>>>(dww, dwb, bidx);
    k3_proj<<<dim3(288,2,4), 256, smem_k3>>>(xprj);
    k_scan_seg   <<<dim3(64,4,NSEG), 96>>>(dtw, dtb, alog, dsv);
    k_scan_prefix<<<dim3(64,4), 96>>>(alog);
    k_scan_fix   <<<dim3(64,4,NSEG-1), 96>>>(dtw, dtb, alog);
    k4_comb<<<dim3(64,48), 96>>>(ssg, ssb, png, pnb, bidx);
    k5_att <<<64, 96>>>(cw1, cb1, cw2, cb2);
    k6_fin <<<dim3(64,48), 256>>>(x, out);
}

// round 12
// speedup vs baseline: 1.1121x; 1.0351x over previous
#include <cuda_runtime.h>
#include <cuda_bf16.h>
#include <cstdint>

#define CC   96
#define LL   2304
#define NBQ  64
#define PXQ  36864
#define NPL  24
#define NSEG 16
#define TCH  9

// ---------------- static scratch ----------------
__device__ float g_a   [NBQ*LL*CC];
__device__ float g_zin [NBQ*LL*CC];
__device__ float g_vf  [NBQ*LL*CC];
__device__ float g_xdbl[NBQ*4*NPL*LL];
__device__ float g_y   [NBQ*LL*CC];
__device__ float g_yo  [NBQ*LL*CC];
__device__ float g_ysum[NBQ*CC];
__device__ float g_att [NBQ*CC];
__device__ float g_sd  [NBQ*4*NSEG*CC];
__device__ float g_hfin[NBQ*4*NSEG*CC*8];
__device__ float g_hin [NBQ*4*NSEG*CC*8];

__device__ __forceinline__ float siluf(float v){ return v * (1.f/(1.f+__expf(-v))); }

__device__ __forceinline__ void fma2(unsigned long long &acc, unsigned long long a, unsigned long long b){
    asm("fma.rn.f32x2 %0,%1,%2,%0;" : "+l"(acc) : "l"(a), "l"(b));
}
__device__ __forceinline__ unsigned long long pack2(float v){
    unsigned long long r; asm("mov.b64 %0,{%1,%1};" : "=l"(r) : "f"(v)); return r;
}
__device__ __forceinline__ float2 unpack2(unsigned long long v){
    float2 r; asm("mov.b64 {%0,%1},%2;" : "=f"(r.x), "=f"(r.y) : "l"(v)); return r;
}
__device__ __forceinline__ void cpasync16(void* dst, const void* src){
    unsigned d = (unsigned)__cvta_generic_to_shared(dst);
    asm volatile("cp.async.ca.shared.global [%0],[%1],16;" :: "r"(d), "l"(src));
}

// =============== K1: LN + BOTH 1x1 convs fused ===============
#define X1S 68
#define W1S 198
__global__ __launch_bounds__(256,2) void k1_gemm(const float* __restrict__ x,
                                                 const float* __restrict__ lg, const float* __restrict__ lb,
                                                 const float* __restrict__ p1w, const float* __restrict__ p1b,
                                                 const float* __restrict__ p2w, const float* __restrict__ p2b)
{
    extern __shared__ float sm[];
    float* Xs = sm;
    float* Ws = sm + 96*X1S;
    __shared__ float mu[64], rs[64];
    __shared__ float b0s[96], b1s[96];
    int q = blockIdx.y, P0 = blockIdx.x*64;
    int bb = P0 / LL, l0 = P0 % LL;
    int qh=(q>>1)*48, qw=(q&1)*48;
    const float* xb = x + (size_t)bb*884736 + (size_t)qh*96 + qw;
    for (int i=threadIdx.x; i<96*64; i+=256){
        int c=i>>6, p=i&63;
        int l=l0+p, h=l/48, w=l%48;
        Xs[c*X1S+p] = xb[(size_t)c*9216 + h*96 + w];
    }
    const float* W0 = p1w + (size_t)q*9216;
    const float* W1 = p2w + (size_t)q*9216;
    for (int i=threadIdx.x; i<9216; i+=256){
        int d=i/96, c=i%96;
        Ws[c*W1S+d]    = W0[i];
        Ws[c*W1S+96+d] = W1[i];
    }
    for (int i=threadIdx.x; i<96; i+=256){ b0s[i]=p1b[q*96+i]; b1s[i]=p2b[q*96+i]; }
    __syncthreads();
    {
        int px = threadIdx.x>>2, part = threadIdx.x&3;
        float s=0.f, ss=0.f;
        const float* col = Xs + px;
        #pragma unroll 8
        for (int cc=part*24; cc<part*24+24; cc++){ float v=col[cc*X1S]; s+=v; ss+=v*v; }
        s  += __shfl_xor_sync(0xffffffffu, s, 1);
        ss += __shfl_xor_sync(0xffffffffu, ss, 1);
        s  += __shfl_xor_sync(0xffffffffu, s, 2);
        ss += __shfl_xor_sync(0xffffffffu, ss, 2);
        if (part==0){
            float m = s*(1.f/96.f);
            mu[px]=m; rs[px]=rsqrtf(ss*(1.f/96.f)-m*m+1e-6f);
        }
    }
    __syncthreads();
    for (int i=threadIdx.x; i<96*64; i+=256){
        int c=i>>6, p=i&63;
        Xs[c*X1S+p] = (Xs[c*X1S+p]-mu[p])*rs[p]*lg[q*96+c] + lb[q*96+c];
    }
    __syncthreads();
    int tp = threadIdx.x & 15, tc = threadIdx.x >> 4;
    unsigned long long acc[6][4];
    #pragma unroll
    for (int j=0;j<6;j++){ acc[j][0]=0ull; acc[j][1]=0ull; acc[j][2]=0ull; acc[j][3]=0ull; }
    const float* xbq = Xs + 4*tp;
    const float* wbq = Ws + 12*tc;
    #pragma unroll 2
    for (int k=0;k<96;k++){
        float4 xv = *(const float4*)(xbq + k*X1S);
        unsigned long long xd0 = pack2(xv.x), xd1 = pack2(xv.y),
                           xd2 = pack2(xv.z), xd3 = pack2(xv.w);
        const unsigned long long* wp = (const unsigned long long*)(wbq + k*W1S);
        #pragma unroll
        for (int j=0;j<6;j++){
            unsigned long long wv = wp[j];
            fma2(acc[j][0], wv, xd0);
            fma2(acc[j][1], wv, xd1);
            fma2(acc[j][2], wv, xd2);
            fma2(acc[j][3], wv, xd3);
        }
    }
    __syncthreads();
    float* sout = sm;                 // [64][100]
    if (tc < 8){
        #pragma unroll
        for (int j=0;j<6;j++){
            int oc = 12*tc + 2*j;
            #pragma unroll
            for (int i=0;i<4;i++){
                float2 v = unpack2(acc[j][i]);
                sout[(size_t)(4*tp+i)*100 + oc    ] = v.x;
                sout[(size_t)(4*tp+i)*100 + oc + 1] = v.y;
            }
        }
    }
    __syncthreads();
    {
        float* dst = g_a + ((size_t)q*PXQ + P0)*96;
        for (int i=threadIdx.x; i<64*96; i+=256){
            int p=i/96, oc=i%96;
            dst[i] = siluf(sout[p*100+oc] + b0s[oc]);
        }
    }
    __syncthreads();
    if (tc >= 8){
        #pragma unroll
        for (int j=0;j<6;j++){
            int oc = 12*(tc-8) + 2*j;
            #pragma unroll
            for (int i=0;i<4;i++){
                float2 v = unpack2(acc[j][i]);
                sout[(size_t)(4*tp+i)*100 + oc    ] = v.x;
                sout[(size_t)(4*tp+i)*100 + oc + 1] = v.y;
            }
        }
    }
    __syncthreads();
    {
        float* dst = g_zin + ((size_t)q*PXQ + P0)*96;
        for (int i=threadIdx.x; i<64*96; i+=256){
            int p=i/96, oc=i%96;
            dst[i] = sout[p*100+oc] + b1s[oc];
        }
    }
}

// =============== K2: depthwise 3x3 + bias + silu + pre-transform; zeros g_y ===============
__global__ __launch_bounds__(256) void k2_dw(const float* __restrict__ dww, const float* __restrict__ dwb,
                                             const int* __restrict__ bidx)
{
    extern __shared__ float rows[];
    __shared__ float wsm[96*9];
    __shared__ float bsm[96];
    int qb = blockIdx.x, q = qb>>4, hr = blockIdx.y;
    if (blockIdx.x==0 && blockIdx.y==0)
        for (int i=threadIdx.x; i<NBQ*CC; i+=256) g_ysum[i]=0.f;
    {
        float* yz = g_y + ((size_t)qb*LL + hr*48)*96;
        for (int i=threadIdx.x; i<48*96; i+=256) yz[i]=0.f;
    }
    for (int i=threadIdx.x; i<96*9; i+=256) wsm[i]=dww[q*96*9 + i];
    for (int i=threadIdx.x; i<96;   i+=256) bsm[i]=dwb[q*96 + i];
    for (int dy=0; dy<3; dy++){
        int hh = hr-1+dy;
        if (hh>=0 && hh<48){
            const float* src = g_zin + ((size_t)qb*LL + hh*48)*96;
            for (int i=threadIdx.x; i<48*96; i+=256) rows[dy*4608+i]=src[i];
        } else {
            for (int i=threadIdx.x; i<48*96; i+=256) rows[dy*4608+i]=0.f;
        }
    }
    __syncthreads();
    bool even = ((bidx[0] & 1) == 0);
    for (int i=threadIdx.x; i<48*96; i+=256){
        int w=i/96, c=i%96;
        float acc = bsm[c];
        #pragma unroll
        for (int dy=0; dy<3; dy++){
            #pragma unroll
            for (int dx=0; dx<3; dx++){
                int ww = w+dx-1;
                if (ww>=0 && ww<48) acc += wsm[c*9+dy*3+dx]*rows[dy*4608 + ww*96 + c];
            }
        }
        float z = siluf(acc);
        int pf = even ? (w*48+hr) : ((47-hr)*48+(47-w));
        g_vf[((size_t)qb*LL + pf)*96 + c] = z;
    }
}

// =============== K3: x-projection GEMM ===============
#define K3XS 132
#define K3WS 50
__global__ __launch_bounds__(256,3) void k3_proj(const float* __restrict__ xprojw)
{
    extern __shared__ float sm[];
    float* Xs = sm;
    float* Ws = sm + 96*K3XS;
    int q = blockIdx.z, src = blockIdx.y, P0 = blockIdx.x*128;
    int b_img = P0 / LL;
    int l0 = P0 % LL;
    const float* vbase = g_vf + (size_t)(q*16 + b_img)*LL*96;
    for (int i=threadIdx.x; i<128*96; i+=256){
        int p=i/96, c=i%96;
        int l = l0 + p;
        int row = src ? ((l%48)*48 + l/48) : l;
        Xs[c*K3XS+p] = vbase[(size_t)row*96 + c];
    }
    for (int i=threadIdx.x; i<48*96; i+=256){
        int oc=i/96, kk=i%96;
        float v=0.f;
        if (oc<44){
            int k = (oc<22)? src : src+2;
            int d = (oc<22)? oc : oc-22;
            v = xprojw[(((size_t)q*4 + k)*22 + d)*96 + kk];
        }
        Ws[kk*K3WS+oc]=v;
    }
    __syncthreads();
    int tp = threadIdx.x & 31, tc = threadIdx.x >> 5;
    unsigned long long acc[3][4];
    #pragma unroll
    for (int j=0;j<3;j++){ acc[j][0]=0ull; acc[j][1]=0ull; acc[j][2]=0ull; acc[j][3]=0ull; }
    const float* xbq = Xs + 4*tp;
    const float* wbq = Ws + 6*tc;
    #pragma unroll 4
    for (int k=0;k<96;k++){
        float4 xv = *(const float4*)(xbq + k*K3XS);
        unsigned long long xd0 = pack2(xv.x), xd1 = pack2(xv.y),
                           xd2 = pack2(xv.z), xd3 = pack2(xv.w);
        const unsigned long long* wp = (const unsigned long long*)(wbq + k*K3WS);
        #pragma unroll
        for (int j=0;j<3;j++){
            unsigned long long wv = wp[j];
            fma2(acc[j][0], wv, xd0);
            fma2(acc[j][1], wv, xd1);
            fma2(acc[j][2], wv, xd2);
            fma2(acc[j][3], wv, xd3);
        }
    }
    int qb = q*16 + b_img;
    int lw = l0 + 4*tp;
    #pragma unroll
    for (int j=0;j<3;j++){
        float2 v0 = unpack2(acc[j][0]);
        float2 v1 = unpack2(acc[j][1]);
        float2 v2 = unpack2(acc[j][2]);
        float2 v3 = unpack2(acc[j][3]);
        #pragma unroll
        for (int h=0; h<2; h++){
            int oc = 6*tc + 2*j + h;
            if (oc>=44) continue;
            int kdir = (oc<22)? src : src+2;
            int d    = (oc<22)? oc : oc-22;
            int plane= (d<6)? d : d+2;
            float* dst = g_xdbl + (((size_t)qb*4 + kdir)*NPL + plane)*LL + lw;
            *(float4*)dst = h ? make_float4(v0.y,v1.y,v2.y,v3.y)
                              : make_float4(v0.x,v1.x,v2.x,v3.x);
        }
    }
}

// =============== Scan pass A: segmented local scan (h0=0) ===============
__global__ __launch_bounds__(96) void k_scan_seg(const float* __restrict__ dtw_g, const float* __restrict__ dtb_g,
                                                 const float* __restrict__ alog_g, const float* __restrict__ ds_g)
{
    __shared__ float s_u [2][16*96];
    __shared__ float s_xd[2][NPL*16];
    int qb = blockIdx.x, k = blockIdx.y, seg = blockIdx.z, q = qb>>4;
    int c = threadIdx.x;
    int pidx = (q*4+k)*96 + c;
    float dtw[6];
    #pragma unroll
    for (int r=0;r<6;r++) dtw[r]=dtw_g[pidx*6+r];
    float dtb = dtb_g[pidx];
    float Ac[8];
    #pragma unroll
    for (int n=0;n<8;n++) Ac[n] = -__expf(alog_g[pidx*8+n]);
    float Dv = ds_g[pidx];
    const float* u_base  = g_vf + (size_t)qb*LL*96;
    const float* xd_base = g_xdbl + ((size_t)qb*4+k)*NPL*LL;
    float* y_base = g_y + (size_t)qb*LL*96;
    bool rev = (k>=2);
    int kt = k & 1;
    int plane = c>>2, piece = c&3;
    float hs[8];
    #pragma unroll
    for (int n=0;n<8;n++) hs[n]=0.f;
    float sd = 0.f;
    int cg0 = seg*TCH;

    auto load_u = [&](int buf, int sst){
        int a0 = sst/48, b0 = sst%48;
        #pragma unroll
        for (int jj=0;jj<4;jj++){
            int pc = c + 96*jj;
            int off = pc/24, fo = pc%24;
            int row = kt ? ((b0+off)*48 + a0) : (sst+off);
            cpasync16(&s_u[buf][off*96 + fo*4], u_base + (size_t)row*96 + fo*4);
        }
        cpasync16(&s_xd[buf][plane*16 + piece*4], xd_base + (size_t)plane*LL + sst + piece*4);
    };

    {
        int cg = cg0;
        int sst = rev ? (LL - 16*(cg+1)) : 16*cg;
        load_u(0, sst);
        asm volatile("cp.async.commit_group;");
    }
    for (int cs=0; cs<TCH; cs++){
        if (cs<TCH-1){
            int cg = cg0+cs+1;
            int sst = rev ? (LL - 16*(cg+1)) : 16*cg;
            load_u((cs+1) & 1, sst);
            asm volatile("cp.async.commit_group;");
            asm volatile("cp.async.wait_group 1;");
        } else {
            asm volatile("cp.async.wait_group 0;");
        }
        __syncthreads();
        int buf = cs & 1;
        int cg = cg0+cs;
        int sst = rev ? (LL - 16*(cg+1)) : 16*cg;
        int a0 = sst/48, b0 = sst%48;
        const float* xd = &s_xd[buf][0];
        #pragma unroll 4
        for (int j=0;j<16;j++){
            int off = rev ? (15-j) : j;
            float draw = dtb + dtw[0]*xd[0*16+off] + dtw[1]*xd[1*16+off] + dtw[2]*xd[2*16+off]
                             + dtw[3]*xd[3*16+off] + dtw[4]*xd[4*16+off] + dtw[5]*xd[5*16+off];
            float delta = (draw > 15.f) ? draw : __logf(1.f + __expf(draw));
            sd += delta;
            float u = s_u[buf][off*96 + c];
            float du = delta*u;
            float y = Dv*u;
            hs[0] = __expf(delta*Ac[0])*hs[0] + du*xd[( 8)*16+off];  y += hs[0]*xd[(16)*16+off];
            hs[1] = __expf(delta*Ac[1])*hs[1] + du*xd[( 9)*16+off];  y += hs[1]*xd[(17)*16+off];
            hs[2] = __expf(delta*Ac[2])*hs[2] + du*xd[(10)*16+off];  y += hs[2]*xd[(18)*16+off];
            hs[3] = __expf(delta*Ac[3])*hs[3] + du*xd[(11)*16+off];  y += hs[3]*xd[(19)*16+off];
            hs[4] = __expf(delta*Ac[4])*hs[4] + du*xd[(12)*16+off];  y += hs[4]*xd[(20)*16+off];
            hs[5] = __expf(delta*Ac[5])*hs[5] + du*xd[(13)*16+off];  y += hs[5]*xd[(21)*16+off];
            hs[6] = __expf(delta*Ac[6])*hs[6] + du*xd[(14)*16+off];  y += hs[6]*xd[(22)*16+off];
            hs[7] = __expf(delta*Ac[7])*hs[7] + du*xd[(15)*16+off];  y += hs[7]*xd[(23)*16+off];
            int row = kt ? ((b0+off)*48 + a0) : (sst+off);
            atomicAdd(&y_base[(size_t)row*96 + c], y);
        }
        __syncthreads();
    }
    size_t sidx = ((((size_t)qb*4+k)*NSEG+seg)*96 + c);
    g_sd[sidx] = sd;
    #pragma unroll
    for (int n=0;n<8;n++) g_hfin[sidx*8+n] = hs[n];
}

// =============== Scan prefix ===============
__global__ __launch_bounds__(96) void k_scan_prefix(const float* __restrict__ alog_g)
{
    int qb = blockIdx.x, k = blockIdx.y, q = qb>>4;
    int c = threadIdx.x;
    int pidx = (q*4+k)*96 + c;
    float Ac[8];
    #pragma unroll
    for (int n=0;n<8;n++) Ac[n] = -__expf(alog_g[pidx*8+n]);
    float h[8];
    #pragma unroll
    for (int n=0;n<8;n++) h[n]=0.f;
    for (int s=0; s<NSEG; s++){
        size_t sidx = ((((size_t)qb*4+k)*NSEG+s)*96 + c);
        #pragma unroll
        for (int n=0;n<8;n++) g_hin[sidx*8+n] = h[n];
        float sd = g_sd[sidx];
        #pragma unroll
        for (int n=0;n<8;n++) h[n] = __expf(Ac[n]*sd)*h[n] + g_hfin[sidx*8+n];
    }
}

// =============== Scan pass C: carry-in corrections ===============
__global__ __launch_bounds__(96) void k_scan_fix(const float* __restrict__ dtw_g, const float* __restrict__ dtb_g,
                                                 const float* __restrict__ alog_g)
{
    __shared__ float s_xd[2][NPL*16];
    int qb = blockIdx.x, k = blockIdx.y, seg = blockIdx.z+1, q = qb>>4;
    int c = threadIdx.x;
    int pidx = (q*4+k)*96 + c;
    float dtw[6];
    #pragma unroll
    for (int r=0;r<6;r++) dtw[r]=dtw_g[pidx*6+r];
    float dtb = dtb_g[pidx];
    float Ac[8];
    #pragma unroll
    for (int n=0;n<8;n++) Ac[n] = -__expf(alog_g[pidx*8+n]);
    float hin[8];
    {
        size_t sidx = ((((size_t)qb*4+k)*NSEG+seg)*96 + c);
        #pragma unroll
        for (int n=0;n<8;n++) hin[n] = g_hin[sidx*8+n];
    }
    const float* xd_base = g_xdbl + ((size_t)qb*4+k)*NPL*LL;
    float* y_base = g_y + (size_t)qb*LL*96;
    bool rev = (k>=2);
    int kt = k & 1;
    int plane = c>>2, piece = c&3;
    bool pneed = (plane<6) || (plane>=16);
    float cum = 0.f;
    int cg0 = seg*TCH;

    auto load_xd = [&](int buf, int sst){
        if (pneed)
            cpasync16(&s_xd[buf][plane*16 + piece*4], xd_base + (size_t)plane*LL + sst + piece*4);
    };
    {
        int cg = cg0;
        int sst = rev ? (LL - 16*(cg+1)) : 16*cg;
        load_xd(0, sst);
        asm volatile("cp.async.commit_group;");
    }
    for (int cs=0; cs<TCH; cs++){
        if (cs<TCH-1){
            int cg = cg0+cs+1;
            int sst = rev ? (LL - 16*(cg+1)) : 16*cg;
            load_xd((cs+1) & 1, sst);
            asm volatile("cp.async.commit_group;");
            asm volatile("cp.async.wait_group 1;");
        } else {
            asm volatile("cp.async.wait_group 0;");
        }
        __syncthreads();
        int buf = cs & 1;
        int cg = cg0+cs;
        int sst = rev ? (LL - 16*(cg+1)) : 16*cg;
        int a0 = sst/48, b0 = sst%48;
        const float* xd = &s_xd[buf][0];
        #pragma unroll 4
        for (int j=0;j<16;j++){
            int off = rev ? (15-j) : j;
            float draw = dtb + dtw[0]*xd[0*16+off] + dtw[1]*xd[1*16+off] + dtw[2]*xd[2*16+off]
                             + dtw[3]*xd[3*16+off] + dtw[4]*xd[4*16+off] + dtw[5]*xd[5*16+off];
            float delta = (draw > 15.f) ? draw : __logf(1.f + __expf(draw));
            cum += delta;
            float y = 0.f;
            y += xd[(16)*16+off] * (__expf(cum*Ac[0])*hin[0]);
            y += xd[(17)*16+off] * (__expf(cum*Ac[1])*hin[1]);
            y += xd[(18)*16+off] * (__expf(cum*Ac[2])*hin[2]);
            y += xd[(19)*16+off] * (__expf(cum*Ac[3])*hin[3]);
            y += xd[(20)*16+off] * (__expf(cum*Ac[4])*hin[4]);
            y += xd[(21)*16+off] * (__expf(cum*Ac[5])*hin[5]);
            y += xd[(22)*16+off] * (__expf(cum*Ac[6])*hin[6]);
            y += xd[(23)*16+off] * (__expf(cum*Ac[7])*hin[7]);
            int row = kt ? ((b0+off)*48 + a0) : (sst+off);
            atomicAdd(&y_base[(size_t)row*96 + c], y);
        }
        __syncthreads();
    }
}

// =============== K4: ssln LN + p2n LN + a*z + ysum ===============
__global__ __launch_bounds__(96) void k4_comb(const float* __restrict__ g1g, const float* __restrict__ b1g,
                                              const float* __restrict__ g2g, const float* __restrict__ b2g,
                                              const int* __restrict__ bidx)
{
    __shared__ float T[48*97];
    __shared__ float mu1[48], rs1[48], mu2[48], rs2[48];
    __shared__ float G1[96], B1[96], G2[96], B2[96];
    int qb = blockIdx.x, q = qb>>4, hr = blockIdx.y, tid = threadIdx.x;
    bool even = ((bidx[0] & 1) == 0);
    G1[tid]=g1g[q*96+tid]; B1[tid]=b1g[q*96+tid];
    G2[tid]=g2g[q*96+tid]; B2[tid]=b2g[q*96+tid];
    const float* yb = g_y + (size_t)qb*LL*96;
    for (int i=tid; i<48*96; i+=96){
        int w=i/96, c=i%96;
        int pf = even ? (w*48+hr) : ((47-hr)*48+(47-w));
        T[w*97+c] = yb[(size_t)pf*96+c];
    }
    __syncthreads();
    {
        int p = tid>>1, half = tid&1;
        float s=0.f, ss=0.f;
        const float* row = &T[p*97 + half*48];
        #pragma unroll 8
        for (int c=0;c<48;c++){ float v=row[c]; s+=v; ss+=v*v; }
        s  += __shfl_xor_sync(0xffffffffu, s, 1);
        ss += __shfl_xor_sync(0xffffffffu, ss, 1);
        if (half==0){
            float m = s*(1.f/96.f);
            mu1[p]=m; rs1[p]=rsqrtf(ss*(1.f/96.f)-m*m+1e-6f);
        }
    }
    __syncthreads();
    {
        int p = tid>>1, half = tid&1;
        float m1=mu1[p], r1=rs1[p];
        float s=0.f, ss=0.f;
        const float* row = &T[p*97 + half*48];
        const float* gg = &G1[half*48];
        const float* bb = &B1[half*48];
        #pragma unroll 8
        for (int c=0;c<48;c++){ float t=(row[c]-m1)*r1*gg[c]+bb[c]; s+=t; ss+=t*t; }
        s  += __shfl_xor_sync(0xffffffffu, s, 1);
        ss += __shfl_xor_sync(0xffffffffu, ss, 1);
        if (half==0){
            float m = s*(1.f/96.f);
            mu2[p]=m; rs2[p]=rsqrtf(ss*(1.f/96.f)-m*m+1e-6f);
        }
    }
    __syncthreads();
    {
        int c = tid;
        float g1=G1[c], b1=B1[c], g2=G2[c], b2=B2[c];
        float ysum=0.f;
        const float* ab = g_a  + ((size_t)qb*LL + hr*48)*96;
        float*       yo = g_yo + ((size_t)qb*LL + hr*48)*96;
        for (int w=0; w<48; w++){
            float o = T[w*97+c];
            float t  = (o-mu1[w])*rs1[w]*g1 + b1;
            float z2 = (t-mu2[w])*rs2[w]*g2 + b2;
            float a = ab[(size_t)w*96 + c];
            float y = a*z2;
            ysum += y;
            yo[(size_t)w*96 + c] = y;
        }
        atomicAdd(&g_ysum[qb*96+c], ysum);
    }
}

// =============== K5: channel attention ===============
__global__ __launch_bounds__(96) void k5_att(const float* __restrict__ w1, const float* __restrict__ b1,
                                             const float* __restrict__ w2, const float* __restrict__ b2)
{
    __shared__ float sv[96], tv[12];
    int qb = blockIdx.x, q = qb>>4, c = threadIdx.x;
    sv[c] = g_ysum[qb*96+c] * (1.f/2304.f);
    __syncthreads();
    if (c<12){
        float acc = b1[q*12+c];
        #pragma unroll 8
        for (int cc=0; cc<96; cc++) acc += w1[(q*12+c)*96+cc]*sv[cc];
        tv[c] = siluf(acc);
    }
    __syncthreads();
    float acc = b2[q*96+c];
    #pragma unroll
    for (int r=0;r<12;r++) acc += w2[(q*96+c)*12+r]*tv[r];
    g_att[qb*96+c] = 1.f/(1.f+__expf(-acc));
}

// =============== K6: residual + att + transpose to NCHW ===============
__global__ __launch_bounds__(256) void k6_fin(const float* __restrict__ x, float* __restrict__ out)
{
    __shared__ float tile[96*49];
    __shared__ float atts[96];
    int qb = blockIdx.x, q = qb>>4, bb = qb&15, hr = blockIdx.y;
    int qh=(q>>1)*48, qw=(q&1)*48;
    const float* src = g_yo + ((size_t)qb*LL + hr*48)*96;
    for (int i=threadIdx.x; i<48*96; i+=256){
        int w=i/96, c=i%96;
        tile[c*49+w] = src[i];
    }
    for (int i=threadIdx.x; i<96; i+=256) atts[i]=g_att[qb*96+i];
    __syncthreads();
    for (int i=threadIdx.x; i<96*48; i+=256){
        int c=i/48, w=i%48;
        size_t oi = ((size_t)(bb*96+c)*96 + qh+hr)*96 + qw + w;
        out[oi] = x[oi] + tile[c*49+w]*atts[c];
    }
}

// ================================================================
extern "C" void kernel_launch(void* const* d_in, const int* in_sizes, int n_in,
                              void* d_out, int out_size)
{
    const float* x    = (const float*)d_in[0];
    const float* ln_g = (const float*)d_in[1];
    const float* ln_b = (const float*)d_in[2];
    const float* p1w  = (const float*)d_in[3];
    const float* p1b  = (const float*)d_in[4];
    const float* p2w  = (const float*)d_in[5];
    const float* p2b  = (const float*)d_in[6];
    const float* dww  = (const float*)d_in[7];
    const float* dwb  = (const float*)d_in[8];
    const float* xprj = (const float*)d_in[9];
    const float* dtw  = (const float*)d_in[10];
    const float* dtb  = (const float*)d_in[11];
    const float* alog = (const float*)d_in[12];
    const float* dsv  = (const float*)d_in[13];
    const float* ssg  = (const float*)d_in[14];
    const float* ssb  = (const float*)d_in[15];
    const float* png  = (const float*)d_in[16];
    const float* pnb  = (const float*)d_in[17];
    const float* cw1  = (const float*)d_in[18];
    const float* cb1  = (const float*)d_in[19];
    const float* cw2  = (const float*)d_in[20];
    const float* cb2  = (const float*)d_in[21];
    const int*   bidx = (const int*)  d_in[22];
    float* out = (float*)d_out;

    const int smem_k1 = (96*X1S + 96*W1S)*4;
    const int smem_k2 = 3*48*96*4;
    const int smem_k3 = (96*K3XS + 96*K3WS)*4;
    cudaFuncSetAttribute(k1_gemm, cudaFuncAttributeMaxDynamicSharedMemorySize, smem_k1);
    cudaFuncSetAttribute(k2_dw,   cudaFuncAttributeMaxDynamicSharedMemorySize, smem_k2);
    cudaFuncSetAttribute(k3_proj, cudaFuncAttributeMaxDynamicSharedMemorySize, smem_k3);

    k1_gemm<<<dim3(576,4), 256, smem_k1>>>(x, ln_g, ln_b, p1w, p1b, p2w, p2b);
    k2_dw  <<<dim3(64,48), 256, smem_k2>>>(dww, dwb, bidx);
    k3_proj<<<dim3(288,2,4), 256, smem_k3>>>(xprj);
    k_scan_seg   <<<dim3(64,4,NSEG), 96>>>(dtw, dtb, alog, dsv);
    k_scan_prefix<<<dim3(64,4), 96>>>(alog);
    k_scan_fix   <<<dim3(64,4,NSEG-1), 96>>>(dtw, dtb, alog);
    k4_comb<<<dim3(64,48), 96>>>(ssg, ssb, png, pnb, bidx);
    k5_att <<<64, 96>>>(cw1, cb1, cw2, cb2);
    k6_fin <<<dim3(64,48), 256>>>(x, out);
}

// round 13
// speedup vs baseline: 1.2061x; 1.0845x over previous
#include <cuda_runtime.h>
#include <cuda_bf16.h>
#include <cstdint>

#define CC   96
#define LL   2304
#define NBQ  64
#define PXQ  36864
#define NPL  24
#define NSEG 16
#define TCH  9

// ---------------- static scratch ----------------
__device__ float g_a   [NBQ*LL*CC];
__device__ float g_zin [NBQ*LL*CC];
__device__ float g_vf  [NBQ*LL*CC];
__device__ float g_xdbl[NBQ*4*NPL*LL];
__device__ float g_y   [NBQ*LL*CC];
__device__ float g_yo  [NBQ*LL*CC];
__device__ float g_ysum[NBQ*CC];
__device__ float g_att [NBQ*CC];
__device__ float g_sd  [NBQ*4*NSEG*CC];
__device__ float g_hfin[NBQ*4*NSEG*CC*8];
__device__ float g_hin [NBQ*4*NSEG*CC*8];

#define L2E 1.442695041f

__device__ __forceinline__ float siluf(float v){ return v * (1.f/(1.f+__expf(-v))); }
__device__ __forceinline__ float ex2f(float v){ float r; asm("ex2.approx.ftz.f32 %0,%1;" : "=f"(r) : "f"(v)); return r; }

__device__ __forceinline__ void fma2(unsigned long long &acc, unsigned long long a, unsigned long long b){
    asm("fma.rn.f32x2 %0,%1,%2,%0;" : "+l"(acc) : "l"(a), "l"(b));
}
__device__ __forceinline__ unsigned long long pack2(float v){
    unsigned long long r; asm("mov.b64 %0,{%1,%1};" : "=l"(r) : "f"(v)); return r;
}
__device__ __forceinline__ float2 unpack2(unsigned long long v){
    float2 r; asm("mov.b64 {%0,%1},%2;" : "=f"(r.x), "=f"(r.y) : "l"(v)); return r;
}
__device__ __forceinline__ void cpasync16(void* dst, const void* src){
    unsigned d = (unsigned)__cvta_generic_to_shared(dst);
    asm volatile("cp.async.ca.shared.global [%0],[%1],16;" :: "r"(d), "l"(src));
}

// =============== K1: LN + BOTH 1x1 convs fused ===============
#define X1S 68
#define W1S 200
__global__ __launch_bounds__(256,2) void k1_gemm(const float* __restrict__ x,
                                                 const float* __restrict__ lg, const float* __restrict__ lb,
                                                 const float* __restrict__ p1w, const float* __restrict__ p1b,
                                                 const float* __restrict__ p2w, const float* __restrict__ p2b)
{
    extern __shared__ float sm[];
    float* Xs = sm;
    float* Ws = sm + 96*X1S;
    __shared__ float mu[64], rs[64];
    __shared__ float b0s[96], b1s[96];
    int q = blockIdx.y, P0 = blockIdx.x*64;
    int bb = P0 / LL, l0 = P0 % LL;
    int qh=(q>>1)*48, qw=(q&1)*48;
    const float* xb = x + (size_t)bb*884736 + (size_t)qh*96 + qw;
    for (int i=threadIdx.x; i<96*64; i+=256){
        int c=i>>6, p=i&63;
        int l=l0+p, h=l/48, w=l%48;
        Xs[c*X1S+p] = xb[(size_t)c*9216 + h*96 + w];
    }
    const float* W0 = p1w + (size_t)q*9216;
    const float* W1 = p2w + (size_t)q*9216;
    for (int i=threadIdx.x; i<9216; i+=256){
        int d=i/96, c=i%96;
        Ws[c*W1S+d]    = W0[i];
        Ws[c*W1S+96+d] = W1[i];
    }
    for (int i=threadIdx.x; i<96; i+=256){ b0s[i]=p1b[q*96+i]; b1s[i]=p2b[q*96+i]; }
    __syncthreads();
    {
        int px = threadIdx.x>>2, part = threadIdx.x&3;
        float s=0.f, ss=0.f;
        const float* col = Xs + px;
        #pragma unroll 8
        for (int cc=part*24; cc<part*24+24; cc++){ float v=col[cc*X1S]; s+=v; ss+=v*v; }
        s  += __shfl_xor_sync(0xffffffffu, s, 1);
        ss += __shfl_xor_sync(0xffffffffu, ss, 1);
        s  += __shfl_xor_sync(0xffffffffu, s, 2);
        ss += __shfl_xor_sync(0xffffffffu, ss, 2);
        if (part==0){
            float m = s*(1.f/96.f);
            mu[px]=m; rs[px]=rsqrtf(ss*(1.f/96.f)-m*m+1e-6f);
        }
    }
    __syncthreads();
    for (int i=threadIdx.x; i<96*64; i+=256){
        int c=i>>6, p=i&63;
        Xs[c*X1S+p] = (Xs[c*X1S+p]-mu[p])*rs[p]*lg[q*96+c] + lb[q*96+c];
    }
    __syncthreads();
    int tp = threadIdx.x & 15, tc = threadIdx.x >> 4;
    unsigned long long acc[6][4];
    #pragma unroll
    for (int j=0;j<6;j++){ acc[j][0]=0ull; acc[j][1]=0ull; acc[j][2]=0ull; acc[j][3]=0ull; }
    const float* xbq = Xs + 4*tp;
    const float* wbq = Ws + 12*tc;      // 48B-aligned; W1S=200 keeps 16B alignment per k
    #pragma unroll 2
    for (int k=0;k<96;k++){
        float4 xv = *(const float4*)(xbq + k*X1S);
        unsigned long long xd0 = pack2(xv.x), xd1 = pack2(xv.y),
                           xd2 = pack2(xv.z), xd3 = pack2(xv.w);
        const float* wr = wbq + k*W1S;
        ulonglong2 wA = *(const ulonglong2*)(wr);      // pairs 0,1
        ulonglong2 wB = *(const ulonglong2*)(wr+4);    // pairs 2,3
        ulonglong2 wC = *(const ulonglong2*)(wr+8);    // pairs 4,5
        unsigned long long wv[6] = {wA.x,wA.y,wB.x,wB.y,wC.x,wC.y};
        #pragma unroll
        for (int j=0;j<6;j++){
            fma2(acc[j][0], wv[j], xd0);
            fma2(acc[j][1], wv[j], xd1);
            fma2(acc[j][2], wv[j], xd2);
            fma2(acc[j][3], wv[j], xd3);
        }
    }
    __syncthreads();
    float* sout = sm;                 // [64][100]
    if (tc < 8){
        #pragma unroll
        for (int j=0;j<6;j++){
            int oc = 12*tc + 2*j;
            #pragma unroll
            for (int i=0;i<4;i++){
                float2 v = unpack2(acc[j][i]);
                sout[(size_t)(4*tp+i)*100 + oc    ] = v.x;
                sout[(size_t)(4*tp+i)*100 + oc + 1] = v.y;
            }
        }
    }
    __syncthreads();
    {
        float* dst = g_a + ((size_t)q*PXQ + P0)*96;
        for (int i=threadIdx.x; i<64*96; i+=256){
            int p=i/96, oc=i%96;
            dst[i] = siluf(sout[p*100+oc] + b0s[oc]);
        }
    }
    __syncthreads();
    if (tc >= 8){
        #pragma unroll
        for (int j=0;j<6;j++){
            int oc = 12*(tc-8) + 2*j;
            #pragma unroll
            for (int i=0;i<4;i++){
                float2 v = unpack2(acc[j][i]);
                sout[(size_t)(4*tp+i)*100 + oc    ] = v.x;
                sout[(size_t)(4*tp+i)*100 + oc + 1] = v.y;
            }
        }
    }
    __syncthreads();
    {
        float* dst = g_zin + ((size_t)q*PXQ + P0)*96;
        for (int i=threadIdx.x; i<64*96; i+=256){
            int p=i/96, oc=i%96;
            dst[i] = sout[p*100+oc] + b1s[oc];
        }
    }
}

// =============== K2: depthwise 3x3 + bias + silu + pre-transform; zeros g_y ===============
__global__ __launch_bounds__(256) void k2_dw(const float* __restrict__ dww, const float* __restrict__ dwb,
                                             const int* __restrict__ bidx)
{
    extern __shared__ float rows[];
    __shared__ float wsm[96*9];
    __shared__ float bsm[96];
    int qb = blockIdx.x, q = qb>>4, hr = blockIdx.y;
    if (blockIdx.x==0 && blockIdx.y==0)
        for (int i=threadIdx.x; i<NBQ*CC; i+=256) g_ysum[i]=0.f;
    {
        float* yz = g_y + ((size_t)qb*LL + hr*48)*96;
        for (int i=threadIdx.x; i<48*96; i+=256) yz[i]=0.f;
    }
    for (int i=threadIdx.x; i<96*9; i+=256) wsm[i]=dww[q*96*9 + i];
    for (int i=threadIdx.x; i<96;   i+=256) bsm[i]=dwb[q*96 + i];
    for (int dy=0; dy<3; dy++){
        int hh = hr-1+dy;
        if (hh>=0 && hh<48){
            const float* src = g_zin + ((size_t)qb*LL + hh*48)*96;
            for (int i=threadIdx.x; i<48*96; i+=256) rows[dy*4608+i]=src[i];
        } else {
            for (int i=threadIdx.x; i<48*96; i+=256) rows[dy*4608+i]=0.f;
        }
    }
    __syncthreads();
    bool even = ((bidx[0] & 1) == 0);
    for (int i=threadIdx.x; i<48*96; i+=256){
        int w=i/96, c=i%96;
        float acc = bsm[c];
        #pragma unroll
        for (int dy=0; dy<3; dy++){
            #pragma unroll
            for (int dx=0; dx<3; dx++){
                int ww = w+dx-1;
                if (ww>=0 && ww<48) acc += wsm[c*9+dy*3+dx]*rows[dy*4608 + ww*96 + c];
            }
        }
        float z = siluf(acc);
        int pf = even ? (w*48+hr) : ((47-hr)*48+(47-w));
        g_vf[((size_t)qb*LL + pf)*96 + c] = z;
    }
}

// =============== K3: x-projection GEMM ===============
#define K3XS 132
#define K3WS 50
__global__ __launch_bounds__(256,3) void k3_proj(const float* __restrict__ xprojw)
{
    extern __shared__ float sm[];
    float* Xs = sm;
    float* Ws = sm + 96*K3XS;
    int q = blockIdx.z, src = blockIdx.y, P0 = blockIdx.x*128;
    int b_img = P0 / LL;
    int l0 = P0 % LL;
    const float* vbase = g_vf + (size_t)(q*16 + b_img)*LL*96;
    for (int i=threadIdx.x; i<128*96; i+=256){
        int p=i/96, c=i%96;
        int l = l0 + p;
        int row = src ? ((l%48)*48 + l/48) : l;
        Xs[c*K3XS+p] = vbase[(size_t)row*96 + c];
    }
    for (int i=threadIdx.x; i<48*96; i+=256){
        int oc=i/96, kk=i%96;
        float v=0.f;
        if (oc<44){
            int k = (oc<22)? src : src+2;
            int d = (oc<22)? oc : oc-22;
            v = xprojw[(((size_t)q*4 + k)*22 + d)*96 + kk];
        }
        Ws[kk*K3WS+oc]=v;
    }
    __syncthreads();
    int tp = threadIdx.x & 31, tc = threadIdx.x >> 5;
    unsigned long long acc[3][4];
    #pragma unroll
    for (int j=0;j<3;j++){ acc[j][0]=0ull; acc[j][1]=0ull; acc[j][2]=0ull; acc[j][3]=0ull; }
    const float* xbq = Xs + 4*tp;
    const float* wbq = Ws + 6*tc;
    #pragma unroll 4
    for (int k=0;k<96;k++){
        float4 xv = *(const float4*)(xbq + k*K3XS);
        unsigned long long xd0 = pack2(xv.x), xd1 = pack2(xv.y),
                           xd2 = pack2(xv.z), xd3 = pack2(xv.w);
        const unsigned long long* wp = (const unsigned long long*)(wbq + k*K3WS);
        #pragma unroll
        for (int j=0;j<3;j++){
            unsigned long long wv = wp[j];
            fma2(acc[j][0], wv, xd0);
            fma2(acc[j][1], wv, xd1);
            fma2(acc[j][2], wv, xd2);
            fma2(acc[j][3], wv, xd3);
        }
    }
    int qb = q*16 + b_img;
    int lw = l0 + 4*tp;
    #pragma unroll
    for (int j=0;j<3;j++){
        float2 v0 = unpack2(acc[j][0]);
        float2 v1 = unpack2(acc[j][1]);
        float2 v2 = unpack2(acc[j][2]);
        float2 v3 = unpack2(acc[j][3]);
        #pragma unroll
        for (int h=0; h<2; h++){
            int oc = 6*tc + 2*j + h;
            if (oc>=44) continue;
            int kdir = (oc<22)? src : src+2;
            int d    = (oc<22)? oc : oc-22;
            int plane= (d<6)? d : d+2;
            float* dst = g_xdbl + (((size_t)qb*4 + kdir)*NPL + plane)*LL + lw;
            *(float4*)dst = h ? make_float4(v0.y,v1.y,v2.y,v3.y)
                              : make_float4(v0.x,v1.x,v2.x,v3.x);
        }
    }
}

// =============== Scan pass A: segmented local scan (h0=0) ===============
__global__ __launch_bounds__(96) void k_scan_seg(const float* __restrict__ dtw_g, const float* __restrict__ dtb_g,
                                                 const float* __restrict__ alog_g, const float* __restrict__ ds_g)
{
    __shared__ float s_u [2][16*96];
    __shared__ float s_xd[2][NPL*16];
    int qb = blockIdx.x, k = blockIdx.y, seg = blockIdx.z, q = qb>>4;
    int c = threadIdx.x;
    int pidx = (q*4+k)*96 + c;
    float dtw[6];
    #pragma unroll
    for (int r=0;r<6;r++) dtw[r]=dtw_g[pidx*6+r];
    float dtb = dtb_g[pidx];
    float Acl[8];
    #pragma unroll
    for (int n=0;n<8;n++) Acl[n] = -L2E*__expf(alog_g[pidx*8+n]);
    float Dv = ds_g[pidx];
    const float* u_base  = g_vf + (size_t)qb*LL*96;
    const float* xd_base = g_xdbl + ((size_t)qb*4+k)*NPL*LL;
    float* y_base = g_y + (size_t)qb*LL*96;
    bool rev = (k>=2);
    int kt = k & 1;
    int plane = c>>2, piece = c&3;
    float hs[8];
    #pragma unroll
    for (int n=0;n<8;n++) hs[n]=0.f;
    float sd = 0.f;
    int cg0 = seg*TCH;

    auto load_u = [&](int buf, int sst){
        int a0 = sst/48, b0 = sst%48;
        #pragma unroll
        for (int jj=0;jj<4;jj++){
            int pc = c + 96*jj;
            int off = pc/24, fo = pc%24;
            int row = kt ? ((b0+off)*48 + a0) : (sst+off);
            cpasync16(&s_u[buf][off*96 + fo*4], u_base + (size_t)row*96 + fo*4);
        }
        cpasync16(&s_xd[buf][plane*16 + piece*4], xd_base + (size_t)plane*LL + sst + piece*4);
    };

    {
        int cg = cg0;
        int sst = rev ? (LL - 16*(cg+1)) : 16*cg;
        load_u(0, sst);
        asm volatile("cp.async.commit_group;");
    }
    for (int cs=0; cs<TCH; cs++){
        if (cs<TCH-1){
            int cg = cg0+cs+1;
            int sst = rev ? (LL - 16*(cg+1)) : 16*cg;
            load_u((cs+1) & 1, sst);
            asm volatile("cp.async.commit_group;");
            asm volatile("cp.async.wait_group 1;");
        } else {
            asm volatile("cp.async.wait_group 0;");
        }
        __syncthreads();
        int buf = cs & 1;
        int cg = cg0+cs;
        int sst = rev ? (LL - 16*(cg+1)) : 16*cg;
        int a0 = sst/48, b0 = sst%48;
        const float* xd = &s_xd[buf][0];
        #pragma unroll 4
        for (int j=0;j<16;j++){
            int off = rev ? (15-j) : j;
            float draw = dtb + dtw[0]*xd[0*16+off] + dtw[1]*xd[1*16+off] + dtw[2]*xd[2*16+off]
                             + dtw[3]*xd[3*16+off] + dtw[4]*xd[4*16+off] + dtw[5]*xd[5*16+off];
            float delta = (draw > 15.f) ? draw : __logf(1.f + __expf(draw));
            sd += delta;
            float u = s_u[buf][off*96 + c];
            float du = delta*u;
            float y = Dv*u;
            hs[0] = ex2f(delta*Acl[0])*hs[0] + du*xd[( 8)*16+off];  y += hs[0]*xd[(16)*16+off];
            hs[1] = ex2f(delta*Acl[1])*hs[1] + du*xd[( 9)*16+off];  y += hs[1]*xd[(17)*16+off];
            hs[2] = ex2f(delta*Acl[2])*hs[2] + du*xd[(10)*16+off];  y += hs[2]*xd[(18)*16+off];
            hs[3] = ex2f(delta*Acl[3])*hs[3] + du*xd[(11)*16+off];  y += hs[3]*xd[(19)*16+off];
            hs[4] = ex2f(delta*Acl[4])*hs[4] + du*xd[(12)*16+off];  y += hs[4]*xd[(20)*16+off];
            hs[5] = ex2f(delta*Acl[5])*hs[5] + du*xd[(13)*16+off];  y += hs[5]*xd[(21)*16+off];
            hs[6] = ex2f(delta*Acl[6])*hs[6] + du*xd[(14)*16+off];  y += hs[6]*xd[(22)*16+off];
            hs[7] = ex2f(delta*Acl[7])*hs[7] + du*xd[(15)*16+off];  y += hs[7]*xd[(23)*16+off];
            int row = kt ? ((b0+off)*48 + a0) : (sst+off);
            atomicAdd(&y_base[(size_t)row*96 + c], y);
        }
        __syncthreads();
    }
    size_t sidx = ((((size_t)qb*4+k)*NSEG+seg)*96 + c);
    g_sd[sidx] = sd;
    #pragma unroll
    for (int n=0;n<8;n++) g_hfin[sidx*8+n] = hs[n];
}

// =============== Scan prefix ===============
__global__ __launch_bounds__(96) void k_scan_prefix(const float* __restrict__ alog_g)
{
    int qb = blockIdx.x, k = blockIdx.y, q = qb>>4;
    int c = threadIdx.x;
    int pidx = (q*4+k)*96 + c;
    float Acl[8];
    #pragma unroll
    for (int n=0;n<8;n++) Acl[n] = -L2E*__expf(alog_g[pidx*8+n]);
    float h[8];
    #pragma unroll
    for (int n=0;n<8;n++) h[n]=0.f;
    for (int s=0; s<NSEG; s++){
        size_t sidx = ((((size_t)qb*4+k)*NSEG+s)*96 + c);
        #pragma unroll
        for (int n=0;n<8;n++) g_hin[sidx*8+n] = h[n];
        float sd = g_sd[sidx];
        #pragma unroll
        for (int n=0;n<8;n++) h[n] = ex2f(Acl[n]*sd)*h[n] + g_hfin[sidx*8+n];
    }
}

// =============== Scan pass C: carry-in corrections ===============
__global__ __launch_bounds__(96) void k_scan_fix(const float* __restrict__ dtw_g, const float* __restrict__ dtb_g,
                                                 const float* __restrict__ alog_g)
{
    __shared__ float s_xd[2][NPL*16];
    int qb = blockIdx.x, k = blockIdx.y, seg = blockIdx.z+1, q = qb>>4;
    int c = threadIdx.x;
    int pidx = (q*4+k)*96 + c;
    float dtw[6];
    #pragma unroll
    for (int r=0;r<6;r++) dtw[r]=dtw_g[pidx*6+r];
    float dtb = dtb_g[pidx];
    float Acl[8];
    #pragma unroll
    for (int n=0;n<8;n++) Acl[n] = -L2E*__expf(alog_g[pidx*8+n]);
    float hin[8];
    {
        size_t sidx = ((((size_t)qb*4+k)*NSEG+seg)*96 + c);
        #pragma unroll
        for (int n=0;n<8;n++) hin[n] = g_hin[sidx*8+n];
    }
    const float* xd_base = g_xdbl + ((size_t)qb*4+k)*NPL*LL;
    float* y_base = g_y + (size_t)qb*LL*96;
    bool rev = (k>=2);
    int kt = k & 1;
    int plane = c>>2, piece = c&3;
    bool pneed = (plane<6) || (plane>=16);
    float cum = 0.f;
    int cg0 = seg*TCH;

    auto load_xd = [&](int buf, int sst){
        if (pneed)
            cpasync16(&s_xd[buf][plane*16 + piece*4], xd_base + (size_t)plane*LL + sst + piece*4);
    };
    {
        int cg = cg0;
        int sst = rev ? (LL - 16*(cg+1)) : 16*cg;
        load_xd(0, sst);
        asm volatile("cp.async.commit_group;");
    }
    for (int cs=0; cs<TCH; cs++){
        if (cs<TCH-1){
            int cg = cg0+cs+1;
            int sst = rev ? (LL - 16*(cg+1)) : 16*cg;
            load_xd((cs+1) & 1, sst);
            asm volatile("cp.async.commit_group;");
            asm volatile("cp.async.wait_group 1;");
        } else {
            asm volatile("cp.async.wait_group 0;");
        }
        __syncthreads();
        int buf = cs & 1;
        int cg = cg0+cs;
        int sst = rev ? (LL - 16*(cg+1)) : 16*cg;
        int a0 = sst/48, b0 = sst%48;
        const float* xd = &s_xd[buf][0];
        #pragma unroll 4
        for (int j=0;j<16;j++){
            int off = rev ? (15-j) : j;
            float draw = dtb + dtw[0]*xd[0*16+off] + dtw[1]*xd[1*16+off] + dtw[2]*xd[2*16+off]
                             + dtw[3]*xd[3*16+off] + dtw[4]*xd[4*16+off] + dtw[5]*xd[5*16+off];
            float delta = (draw > 15.f) ? draw : __logf(1.f + __expf(draw));
            cum += delta;
            float y = 0.f;
            y += xd[(16)*16+off] * (ex2f(cum*Acl[0])*hin[0]);
            y += xd[(17)*16+off] * (ex2f(cum*Acl[1])*hin[1]);
            y += xd[(18)*16+off] * (ex2f(cum*Acl[2])*hin[2]);
            y += xd[(19)*16+off] * (ex2f(cum*Acl[3])*hin[3]);
            y += xd[(20)*16+off] * (ex2f(cum*Acl[4])*hin[4]);
            y += xd[(21)*16+off] * (ex2f(cum*Acl[5])*hin[5]);
            y += xd[(22)*16+off] * (ex2f(cum*Acl[6])*hin[6]);
            y += xd[(23)*16+off] * (ex2f(cum*Acl[7])*hin[7]);
            int row = kt ? ((b0+off)*48 + a0) : (sst+off);
            atomicAdd(&y_base[(size_t)row*96 + c], y);
        }
        __syncthreads();
    }
}

// =============== K4: ssln LN + p2n LN + a*z + ysum ===============
__global__ __launch_bounds__(96) void k4_comb(const float* __restrict__ g1g, const float* __restrict__ b1g,
                                              const float* __restrict__ g2g, const float* __restrict__ b2g,
                                              const int* __restrict__ bidx)
{
    __shared__ float T[48*97];
    __shared__ float mu1[48], rs1[48], mu2[48], rs2[48];
    __shared__ float G1[96], B1[96], G2[96], B2[96];
    int qb = blockIdx.x, q = qb>>4, hr = blockIdx.y, tid = threadIdx.x;
    bool even = ((bidx[0] & 1) == 0);
    G1[tid]=g1g[q*96+tid]; B1[tid]=b1g[q*96+tid];
    G2[tid]=g2g[q*96+tid]; B2[tid]=b2g[q*96+tid];
    const float* yb = g_y + (size_t)qb*LL*96;
    for (int i=tid; i<48*96; i+=96){
        int w=i/96, c=i%96;
        int pf = even ? (w*48+hr) : ((47-hr)*48+(47-w));
        T[w*97+c] = yb[(size_t)pf*96+c];
    }
    __syncthreads();
    {
        int p = tid>>1, half = tid&1;
        float s=0.f, ss=0.f;
        const float* row = &T[p*97 + half*48];
        #pragma unroll 8
        for (int c=0;c<48;c++){ float v=row[c]; s+=v; ss+=v*v; }
        s  += __shfl_xor_sync(0xffffffffu, s, 1);
        ss += __shfl_xor_sync(0xffffffffu, ss, 1);
        if (half==0){
            float m = s*(1.f/96.f);
            mu1[p]=m; rs1[p]=rsqrtf(ss*(1.f/96.f)-m*m+1e-6f);
        }
    }
    __syncthreads();
    {
        int p = tid>>1, half = tid&1;
        float m1=mu1[p], r1=rs1[p];
        float s=0.f, ss=0.f;
        const float* row = &T[p*97 + half*48];
        const float* gg = &G1[half*48];
        const float* bb = &B1[half*48];
        #pragma unroll 8
        for (int c=0;c<48;c++){ float t=(row[c]-m1)*r1*gg[c]+bb[c]; s+=t; ss+=t*t; }
        s  += __shfl_xor_sync(0xffffffffu, s, 1);
        ss += __shfl_xor_sync(0xffffffffu, ss, 1);
        if (half==0){
            float m = s*(1.f/96.f);
            mu2[p]=m; rs2[p]=rsqrtf(ss*(1.f/96.f)-m*m+1e-6f);
        }
    }
    __syncthreads();
    {
        int c = tid;
        float g1=G1[c], b1=B1[c], g2=G2[c], b2=B2[c];
        float ysum=0.f;
        const float* ab = g_a  + ((size_t)qb*LL + hr*48)*96;
        float*       yo = g_yo + ((size_t)qb*LL + hr*48)*96;
        for (int w=0; w<48; w++){
            float o = T[w*97+c];
            float t  = (o-mu1[w])*rs1[w]*g1 + b1;
            float z2 = (t-mu2[w])*rs2[w]*g2 + b2;
            float a = ab[(size_t)w*96 + c];
            float y = a*z2;
            ysum += y;
            yo[(size_t)w*96 + c] = y;
        }
        atomicAdd(&g_ysum[qb*96+c], ysum);
    }
}

// =============== K5: channel attention ===============
__global__ __launch_bounds__(96) void k5_att(const float* __restrict__ w1, const float* __restrict__ b1,
                                             const float* __restrict__ w2, const float* __restrict__ b2)
{
    __shared__ float sv[96], tv[12];
    int qb = blockIdx.x, q = qb>>4, c = threadIdx.x;
    sv[c] = g_ysum[qb*96+c] * (1.f/2304.f);
    __syncthreads();
    if (c<12){
        float acc = b1[q*12+c];
        #pragma unroll 8
        for (int cc=0; cc<96; cc++) acc += w1[(q*12+c)*96+cc]*sv[cc];
        tv[c] = siluf(acc);
    }
    __syncthreads();
    float acc = b2[q*96+c];
    #pragma unroll
    for (int r=0;r<12;r++) acc += w2[(q*96+c)*12+r]*tv[r];
    g_att[qb*96+c] = 1.f/(1.f+__expf(-acc));
}

// =============== K6: residual + att + transpose to NCHW ===============
__global__ __launch_bounds__(256) void k6_fin(const float* __restrict__ x, float* __restrict__ out)
{
    __shared__ float tile[96*49];
    __shared__ float atts[96];
    int qb = blockIdx.x, q = qb>>4, bb = qb&15, hr = blockIdx.y;
    int qh=(q>>1)*48, qw=(q&1)*48;
    const float* src = g_yo + ((size_t)qb*LL + hr*48)*96;
    for (int i=threadIdx.x; i<48*96; i+=256){
        int w=i/96, c=i%96;
        tile[c*49+w] = src[i];
    }
    for (int i=threadIdx.x; i<96; i+=256) atts[i]=g_att[qb*96+i];
    __syncthreads();
    for (int i=threadIdx.x; i<96*48; i+=256){
        int c=i/48, w=i%48;
        size_t oi = ((size_t)(bb*96+c)*96 + qh+hr)*96 + qw + w;
        out[oi] = x[oi] + tile[c*49+w]*atts[c];
    }
}

// ================================================================
extern "C" void kernel_launch(void* const* d_in, const int* in_sizes, int n_in,
                              void* d_out, int out_size)
{
    const float* x    = (const float*)d_in[0];
    const float* ln_g = (const float*)d_in[1];
    const float* ln_b = (const float*)d_in[2];
    const float* p1w  = (const float*)d_in[3];
    const float* p1b  = (const float*)d_in[4];
    const float* p2w  = (const float*)d_in[5];
    const float* p2b  = (const float*)d_in[6];
    const float* dww  = (const float*)d_in[7];
    const float* dwb  = (const float*)d_in[8];
    const float* xprj = (const float*)d_in[9];
    const float* dtw  = (const float*)d_in[10];
    const float* dtb  = (const float*)d_in[11];
    const float* alog = (const float*)d_in[12];
    const float* dsv  = (const float*)d_in[13];
    const float* ssg  = (const float*)d_in[14];
    const float* ssb  = (const float*)d_in[15];
    const float* png  = (const float*)d_in[16];
    const float* pnb  = (const float*)d_in[17];
    const float* cw1  = (const float*)d_in[18];
    const float* cb1  = (const float*)d_in[19];
    const float* cw2  = (const float*)d_in[20];
    const float* cb2  = (const float*)d_in[21];
    const int*   bidx = (const int*)  d_in[22];
    float* out = (float*)d_out;

    const int smem_k1 = (96*X1S + 96*W1S)*4;     // 102912
    const int smem_k2 = 3*48*96*4;
    const int smem_k3 = (96*K3XS + 96*K3WS)*4;
    cudaFuncSetAttribute(k1_gemm, cudaFuncAttributeMaxDynamicSharedMemorySize, smem_k1);
    cudaFuncSetAttribute(k2_dw,   cudaFuncAttributeMaxDynamicSharedMemorySize, smem_k2);
    cudaFuncSetAttribute(k3_proj, cudaFuncAttributeMaxDynamicSharedMemorySize, smem_k3);

    k1_gemm<<<dim3(576,4), 256, smem_k1>>>(x, ln_g, ln_b, p1w, p1b, p2w, p2b);
    k2_dw  <<<dim3(64,48), 256, smem_k2>>>(dww, dwb, bidx);
    k3_proj<<<dim3(288,2,4), 256, smem_k3>>>(xprj);
    k_scan_seg   <<<dim3(64,4,NSEG), 96>>>(dtw, dtb, alog, dsv);
    k_scan_prefix<<<dim3(64,4), 96>>>(alog);
    k_scan_fix   <<<dim3(64,4,NSEG-1), 96>>>(dtw, dtb, alog);
    k4_comb<<<dim3(64,48), 96>>>(ssg, ssb, png, pnb, bidx);
    k5_att <<<64, 96>>>(cw1, cb1, cw2, cb2);
    k6_fin <<<dim3(64,48), 256>>>(x, out);
}

// round 14
// speedup vs baseline: 1.2559x; 1.0412x over previous
#include <cuda_runtime.h>
#include <cuda_bf16.h>
#include <cstdint>

#define CC   96
#define LL   2304
#define NBQ  64
#define PXQ  36864
#define NPL  24
#define NSEG 16
#define TCH  9

// ---------------- static scratch ----------------
__device__ float g_a   [NBQ*LL*CC];
__device__ float g_zin [NBQ*LL*CC];
__device__ float g_vf  [NBQ*LL*CC];
__device__ float g_xdbl[NBQ*4*NPL*LL];
__device__ float g_y   [NBQ*LL*CC];
__device__ float g_yo  [NBQ*LL*CC];
__device__ float g_ysum[NBQ*CC];
__device__ float g_att [NBQ*CC];
__device__ float g_sd  [NBQ*4*NSEG*CC];
__device__ float g_hfin[NBQ*4*NSEG*CC*8];
__device__ float g_hin [NBQ*4*NSEG*CC*8];

#define L2E 1.442695041f

__device__ __forceinline__ float siluf(float v){ return v * (1.f/(1.f+__expf(-v))); }
__device__ __forceinline__ float ex2f(float v){ float r; asm("ex2.approx.ftz.f32 %0,%1;" : "=f"(r) : "f"(v)); return r; }

__device__ __forceinline__ void fma2(unsigned long long &acc, unsigned long long a, unsigned long long b){
    asm("fma.rn.f32x2 %0,%1,%2,%0;" : "+l"(acc) : "l"(a), "l"(b));
}
__device__ __forceinline__ unsigned long long pack2(float v){
    unsigned long long r; asm("mov.b64 %0,{%1,%1};" : "=l"(r) : "f"(v)); return r;
}
__device__ __forceinline__ float2 unpack2(unsigned long long v){
    float2 r; asm("mov.b64 {%0,%1},%2;" : "=f"(r.x), "=f"(r.y) : "l"(v)); return r;
}
__device__ __forceinline__ void cpasync16(void* dst, const void* src){
    unsigned d = (unsigned)__cvta_generic_to_shared(dst);
    asm volatile("cp.async.ca.shared.global [%0],[%1],16;" :: "r"(d), "l"(src));
}

// =============== K1: LN + BOTH 1x1 convs fused ===============
#define X1S 68
#define W1S 200
__global__ __launch_bounds__(256,2) void k1_gemm(const float* __restrict__ x,
                                                 const float* __restrict__ lg, const float* __restrict__ lb,
                                                 const float* __restrict__ p1w, const float* __restrict__ p1b,
                                                 const float* __restrict__ p2w, const float* __restrict__ p2b)
{
    extern __shared__ float sm[];
    float* Xs = sm;
    float* Ws = sm + 96*X1S;
    __shared__ float mu[64], rs[64];
    __shared__ float b0s[96], b1s[96];
    int q = blockIdx.y, P0 = blockIdx.x*64;
    int bb = P0 / LL, l0 = P0 % LL;
    int qh=(q>>1)*48, qw=(q&1)*48;
    const float* xb = x + (size_t)bb*884736 + (size_t)qh*96 + qw;
    for (int i=threadIdx.x; i<96*64; i+=256){
        int c=i>>6, p=i&63;
        int l=l0+p, h=l/48, w=l%48;
        Xs[c*X1S+p] = xb[(size_t)c*9216 + h*96 + w];
    }
    const float* W0 = p1w + (size_t)q*9216;
    const float* W1 = p2w + (size_t)q*9216;
    for (int i=threadIdx.x; i<9216; i+=256){
        int d=i/96, c=i%96;
        Ws[c*W1S+d]    = W0[i];
        Ws[c*W1S+96+d] = W1[i];
    }
    for (int i=threadIdx.x; i<96; i+=256){ b0s[i]=p1b[q*96+i]; b1s[i]=p2b[q*96+i]; }
    __syncthreads();
    {
        int px = threadIdx.x>>2, part = threadIdx.x&3;
        float s=0.f, ss=0.f;
        const float* col = Xs + px;
        #pragma unroll 8
        for (int cc=part*24; cc<part*24+24; cc++){ float v=col[cc*X1S]; s+=v; ss+=v*v; }
        s  += __shfl_xor_sync(0xffffffffu, s, 1);
        ss += __shfl_xor_sync(0xffffffffu, ss, 1);
        s  += __shfl_xor_sync(0xffffffffu, s, 2);
        ss += __shfl_xor_sync(0xffffffffu, ss, 2);
        if (part==0){
            float m = s*(1.f/96.f);
            mu[px]=m; rs[px]=rsqrtf(ss*(1.f/96.f)-m*m+1e-6f);
        }
    }
    __syncthreads();
    for (int i=threadIdx.x; i<96*64; i+=256){
        int c=i>>6, p=i&63;
        Xs[c*X1S+p] = (Xs[c*X1S+p]-mu[p])*rs[p]*lg[q*96+c] + lb[q*96+c];
    }
    __syncthreads();
    int tp = threadIdx.x & 15, tc = threadIdx.x >> 4;
    unsigned long long acc[6][4];
    #pragma unroll
    for (int j=0;j<6;j++){ acc[j][0]=0ull; acc[j][1]=0ull; acc[j][2]=0ull; acc[j][3]=0ull; }
    const float* xbq = Xs + 4*tp;
    const float* wbq = Ws + 12*tc;
    #pragma unroll 2
    for (int k=0;k<96;k++){
        float4 xv = *(const float4*)(xbq + k*X1S);
        unsigned long long xd0 = pack2(xv.x), xd1 = pack2(xv.y),
                           xd2 = pack2(xv.z), xd3 = pack2(xv.w);
        const float* wr = wbq + k*W1S;
        ulonglong2 wA = *(const ulonglong2*)(wr);
        ulonglong2 wB = *(const ulonglong2*)(wr+4);
        ulonglong2 wC = *(const ulonglong2*)(wr+8);
        unsigned long long wv[6] = {wA.x,wA.y,wB.x,wB.y,wC.x,wC.y};
        #pragma unroll
        for (int j=0;j<6;j++){
            fma2(acc[j][0], wv[j], xd0);
            fma2(acc[j][1], wv[j], xd1);
            fma2(acc[j][2], wv[j], xd2);
            fma2(acc[j][3], wv[j], xd3);
        }
    }
    __syncthreads();
    float* sout = sm;                 // [64][100]
    if (tc < 8){
        #pragma unroll
        for (int j=0;j<6;j++){
            int oc = 12*tc + 2*j;
            #pragma unroll
            for (int i=0;i<4;i++){
                float2 v = unpack2(acc[j][i]);
                sout[(size_t)(4*tp+i)*100 + oc    ] = v.x;
                sout[(size_t)(4*tp+i)*100 + oc + 1] = v.y;
            }
        }
    }
    __syncthreads();
    {
        float* dst = g_a + ((size_t)q*PXQ + P0)*96;
        for (int i=threadIdx.x; i<64*96; i+=256){
            int p=i/96, oc=i%96;
            dst[i] = siluf(sout[p*100+oc] + b0s[oc]);
        }
    }
    __syncthreads();
    if (tc >= 8){
        #pragma unroll
        for (int j=0;j<6;j++){
            int oc = 12*(tc-8) + 2*j;
            #pragma unroll
            for (int i=0;i<4;i++){
                float2 v = unpack2(acc[j][i]);
                sout[(size_t)(4*tp+i)*100 + oc    ] = v.x;
                sout[(size_t)(4*tp+i)*100 + oc + 1] = v.y;
            }
        }
    }
    __syncthreads();
    {
        float* dst = g_zin + ((size_t)q*PXQ + P0)*96;
        for (int i=threadIdx.x; i<64*96; i+=256){
            int p=i/96, oc=i%96;
            dst[i] = sout[p*100+oc] + b1s[oc];
        }
    }
}

// =============== K2: depthwise 3x3 + bias + silu + pre-transform; zeros g_y ===============
__global__ __launch_bounds__(256) void k2_dw(const float* __restrict__ dww, const float* __restrict__ dwb,
                                             const int* __restrict__ bidx)
{
    extern __shared__ float rows[];
    __shared__ float wsm[96*9];
    __shared__ float bsm[96];
    int qb = blockIdx.x, q = qb>>4, hr = blockIdx.y;
    if (blockIdx.x==0 && blockIdx.y==0)
        for (int i=threadIdx.x; i<NBQ*CC; i+=256) g_ysum[i]=0.f;
    {
        float* yz = g_y + ((size_t)qb*LL + hr*48)*96;
        for (int i=threadIdx.x; i<48*96; i+=256) yz[i]=0.f;
    }
    for (int i=threadIdx.x; i<96*9; i+=256) wsm[i]=dww[q*96*9 + i];
    for (int i=threadIdx.x; i<96;   i+=256) bsm[i]=dwb[q*96 + i];
    for (int dy=0; dy<3; dy++){
        int hh = hr-1+dy;
        if (hh>=0 && hh<48){
            const float* src = g_zin + ((size_t)qb*LL + hh*48)*96;
            for (int i=threadIdx.x; i<48*96; i+=256) rows[dy*4608+i]=src[i];
        } else {
            for (int i=threadIdx.x; i<48*96; i+=256) rows[dy*4608+i]=0.f;
        }
    }
    __syncthreads();
    bool even = ((bidx[0] & 1) == 0);
    for (int i=threadIdx.x; i<48*96; i+=256){
        int w=i/96, c=i%96;
        float acc = bsm[c];
        #pragma unroll
        for (int dy=0; dy<3; dy++){
            #pragma unroll
            for (int dx=0; dx<3; dx++){
                int ww = w+dx-1;
                if (ww>=0 && ww<48) acc += wsm[c*9+dy*3+dx]*rows[dy*4608 + ww*96 + c];
            }
        }
        float z = siluf(acc);
        int pf = even ? (w*48+hr) : ((47-hr)*48+(47-w));
        g_vf[((size_t)qb*LL + pf)*96 + c] = z;
    }
}

// =============== K3: x-projection GEMM ===============
#define K3XS 132
#define K3WS 50
__global__ __launch_bounds__(256,3) void k3_proj(const float* __restrict__ xprojw)
{
    extern __shared__ float sm[];
    float* Xs = sm;
    float* Ws = sm + 96*K3XS;
    int q = blockIdx.z, src = blockIdx.y, P0 = blockIdx.x*128;
    int b_img = P0 / LL;
    int l0 = P0 % LL;
    const float* vbase = g_vf + (size_t)(q*16 + b_img)*LL*96;
    for (int i=threadIdx.x; i<128*96; i+=256){
        int p=i/96, c=i%96;
        int l = l0 + p;
        int row = src ? ((l%48)*48 + l/48) : l;
        Xs[c*K3XS+p] = vbase[(size_t)row*96 + c];
    }
    for (int i=threadIdx.x; i<48*96; i+=256){
        int oc=i/96, kk=i%96;
        float v=0.f;
        if (oc<44){
            int k = (oc<22)? src : src+2;
            int d = (oc<22)? oc : oc-22;
            v = xprojw[(((size_t)q*4 + k)*22 + d)*96 + kk];
        }
        Ws[kk*K3WS+oc]=v;
    }
    __syncthreads();
    int tp = threadIdx.x & 31, tc = threadIdx.x >> 5;
    unsigned long long acc[3][4];
    #pragma unroll
    for (int j=0;j<3;j++){ acc[j][0]=0ull; acc[j][1]=0ull; acc[j][2]=0ull; acc[j][3]=0ull; }
    const float* xbq = Xs + 4*tp;
    const float* wbq = Ws + 6*tc;
    #pragma unroll 4
    for (int k=0;k<96;k++){
        float4 xv = *(const float4*)(xbq + k*K3XS);
        unsigned long long xd0 = pack2(xv.x), xd1 = pack2(xv.y),
                           xd2 = pack2(xv.z), xd3 = pack2(xv.w);
        const unsigned long long* wp = (const unsigned long long*)(wbq + k*K3WS);
        #pragma unroll
        for (int j=0;j<3;j++){
            unsigned long long wv = wp[j];
            fma2(acc[j][0], wv, xd0);
            fma2(acc[j][1], wv, xd1);
            fma2(acc[j][2], wv, xd2);
            fma2(acc[j][3], wv, xd3);
        }
    }
    int qb = q*16 + b_img;
    int lw = l0 + 4*tp;
    #pragma unroll
    for (int j=0;j<3;j++){
        float2 v0 = unpack2(acc[j][0]);
        float2 v1 = unpack2(acc[j][1]);
        float2 v2 = unpack2(acc[j][2]);
        float2 v3 = unpack2(acc[j][3]);
        #pragma unroll
        for (int h=0; h<2; h++){
            int oc = 6*tc + 2*j + h;
            if (oc>=44) continue;
            int kdir = (oc<22)? src : src+2;
            int d    = (oc<22)? oc : oc-22;
            int plane= (d<6)? d : d+2;
            float* dst = g_xdbl + (((size_t)qb*4 + kdir)*NPL + plane)*LL + lw;
            *(float4*)dst = h ? make_float4(v0.y,v1.y,v2.y,v3.y)
                              : make_float4(v0.x,v1.x,v2.x,v3.x);
        }
    }
}

// =============== Scan pass A: segmented local scan (h0=0), transposed xd reads ===============
__global__ __launch_bounds__(96) void k_scan_seg(const float* __restrict__ dtw_g, const float* __restrict__ dtb_g,
                                                 const float* __restrict__ alog_g, const float* __restrict__ ds_g)
{
    __shared__ float s_u [2][16*96];
    __shared__ float s_xd[2][NPL*16];
    __shared__ float s_x2[2][16*32];      // [off][32]: dts 0-5, pad, B 8-15, C 16-23
    int qb = blockIdx.x, k = blockIdx.y, seg = blockIdx.z, q = qb>>4;
    int c = threadIdx.x;
    int pidx = (q*4+k)*96 + c;
    float dtw[6];
    #pragma unroll
    for (int r=0;r<6;r++) dtw[r]=dtw_g[pidx*6+r];
    float dtb = dtb_g[pidx];
    float Acl[8];
    #pragma unroll
    for (int n=0;n<8;n++) Acl[n] = -L2E*__expf(alog_g[pidx*8+n]);
    float Dv = ds_g[pidx];
    const float* u_base  = g_vf + (size_t)qb*LL*96;
    const float* xd_base = g_xdbl + ((size_t)qb*4+k)*NPL*LL;
    float* y_base = g_y + (size_t)qb*LL*96;
    bool rev = (k>=2);
    int kt = k & 1;
    int plane = c>>2, piece = c&3;
    float hs[8];
    #pragma unroll
    for (int n=0;n<8;n++) hs[n]=0.f;
    float sd = 0.f;
    int cg0 = seg*TCH;

    auto load_u = [&](int buf, int sst){
        int a0 = sst/48, b0 = sst%48;
        #pragma unroll
        for (int jj=0;jj<4;jj++){
            int pc = c + 96*jj;
            int off = pc/24, fo = pc%24;
            int row = kt ? ((b0+off)*48 + a0) : (sst+off);
            cpasync16(&s_u[buf][off*96 + fo*4], u_base + (size_t)row*96 + fo*4);
        }
        cpasync16(&s_xd[buf][plane*16 + piece*4], xd_base + (size_t)plane*LL + sst + piece*4);
    };

    {
        int cg = cg0;
        int sst = rev ? (LL - 16*(cg+1)) : 16*cg;
        load_u(0, sst);
        asm volatile("cp.async.commit_group;");
    }
    int tpp = c>>2, to4 = (c&3)*4;   // transpose assignment
    for (int cs=0; cs<TCH; cs++){
        if (cs<TCH-1){
            int cg = cg0+cs+1;
            int sst = rev ? (LL - 16*(cg+1)) : 16*cg;
            load_u((cs+1) & 1, sst);
            asm volatile("cp.async.commit_group;");
            asm volatile("cp.async.wait_group 1;");
        } else {
            asm volatile("cp.async.wait_group 0;");
        }
        __syncthreads();
        int buf = cs & 1;
        // transpose s_xd[buf] [plane][16] -> s_x2[buf] [off][32]
        {
            float4 v = *(const float4*)&s_xd[buf][tpp*16 + to4];
            float* d = &s_x2[buf][tpp];
            d[(to4  )*32] = v.x;
            d[(to4+1)*32] = v.y;
            d[(to4+2)*32] = v.z;
            d[(to4+3)*32] = v.w;
        }
        __syncthreads();
        int cg = cg0+cs;
        int sst = rev ? (LL - 16*(cg+1)) : 16*cg;
        int a0 = sst/48, b0 = sst%48;
        const float* x2 = &s_x2[buf][0];
        #pragma unroll 4
        for (int j=0;j<16;j++){
            int off = rev ? (15-j) : j;
            const float* xr = x2 + off*32;
            float4 dA = *(const float4*)(xr);
            float2 dB = *(const float2*)(xr+4);
            float draw = dtb + dtw[0]*dA.x + dtw[1]*dA.y + dtw[2]*dA.z
                             + dtw[3]*dA.w + dtw[4]*dB.x + dtw[5]*dB.y;
            float delta = (draw > 15.f) ? draw : __logf(1.f + __expf(draw));
            sd += delta;
            float u = s_u[buf][off*96 + c];
            float du = delta*u;
            float y = Dv*u;
            float4 B0 = *(const float4*)(xr+8);
            float4 B1 = *(const float4*)(xr+12);
            float4 C0 = *(const float4*)(xr+16);
            float4 C1 = *(const float4*)(xr+20);
            hs[0] = ex2f(delta*Acl[0])*hs[0] + du*B0.x;  y += hs[0]*C0.x;
            hs[1] = ex2f(delta*Acl[1])*hs[1] + du*B0.y;  y += hs[1]*C0.y;
            hs[2] = ex2f(delta*Acl[2])*hs[2] + du*B0.z;  y += hs[2]*C0.z;
            hs[3] = ex2f(delta*Acl[3])*hs[3] + du*B0.w;  y += hs[3]*C0.w;
            hs[4] = ex2f(delta*Acl[4])*hs[4] + du*B1.x;  y += hs[4]*C1.x;
            hs[5] = ex2f(delta*Acl[5])*hs[5] + du*B1.y;  y += hs[5]*C1.y;
            hs[6] = ex2f(delta*Acl[6])*hs[6] + du*B1.z;  y += hs[6]*C1.z;
            hs[7] = ex2f(delta*Acl[7])*hs[7] + du*B1.w;  y += hs[7]*C1.w;
            int row = kt ? ((b0+off)*48 + a0) : (sst+off);
            atomicAdd(&y_base[(size_t)row*96 + c], y);
        }
        __syncthreads();
    }
    size_t sidx = ((((size_t)qb*4+k)*NSEG+seg)*96 + c);
    g_sd[sidx] = sd;
    #pragma unroll
    for (int n=0;n<8;n++) g_hfin[sidx*8+n] = hs[n];
}

// =============== Scan prefix ===============
__global__ __launch_bounds__(96) void k_scan_prefix(const float* __restrict__ alog_g)
{
    int qb = blockIdx.x, k = blockIdx.y, q = qb>>4;
    int c = threadIdx.x;
    int pidx = (q*4+k)*96 + c;
    float Acl[8];
    #pragma unroll
    for (int n=0;n<8;n++) Acl[n] = -L2E*__expf(alog_g[pidx*8+n]);
    float h[8];
    #pragma unroll
    for (int n=0;n<8;n++) h[n]=0.f;
    for (int s=0; s<NSEG; s++){
        size_t sidx = ((((size_t)qb*4+k)*NSEG+s)*96 + c);
        #pragma unroll
        for (int n=0;n<8;n++) g_hin[sidx*8+n] = h[n];
        float sd = g_sd[sidx];
        #pragma unroll
        for (int n=0;n<8;n++) h[n] = ex2f(Acl[n]*sd)*h[n] + g_hfin[sidx*8+n];
    }
}

// =============== Scan pass C: carry-in corrections, transposed xd reads ===============
__global__ __launch_bounds__(96) void k_scan_fix(const float* __restrict__ dtw_g, const float* __restrict__ dtb_g,
                                                 const float* __restrict__ alog_g)
{
    __shared__ float s_xd[2][NPL*16];
    __shared__ float s_x2[2][16*32];
    int qb = blockIdx.x, k = blockIdx.y, seg = blockIdx.z+1, q = qb>>4;
    int c = threadIdx.x;
    int pidx = (q*4+k)*96 + c;
    float dtw[6];
    #pragma unroll
    for (int r=0;r<6;r++) dtw[r]=dtw_g[pidx*6+r];
    float dtb = dtb_g[pidx];
    float Acl[8];
    #pragma unroll
    for (int n=0;n<8;n++) Acl[n] = -L2E*__expf(alog_g[pidx*8+n]);
    float hin[8];
    {
        size_t sidx = ((((size_t)qb*4+k)*NSEG+seg)*96 + c);
        #pragma unroll
        for (int n=0;n<8;n++) hin[n] = g_hin[sidx*8+n];
    }
    const float* xd_base = g_xdbl + ((size_t)qb*4+k)*NPL*LL;
    float* y_base = g_y + (size_t)qb*LL*96;
    bool rev = (k>=2);
    int kt = k & 1;
    int plane = c>>2, piece = c&3;
    bool pneed = (plane<6) || (plane>=16);
    float cum = 0.f;
    int cg0 = seg*TCH;

    auto load_xd = [&](int buf, int sst){
        if (pneed)
            cpasync16(&s_xd[buf][plane*16 + piece*4], xd_base + (size_t)plane*LL + sst + piece*4);
    };
    {
        int cg = cg0;
        int sst = rev ? (LL - 16*(cg+1)) : 16*cg;
        load_xd(0, sst);
        asm volatile("cp.async.commit_group;");
    }
    int tpp = c>>2, to4 = (c&3)*4;
    for (int cs=0; cs<TCH; cs++){
        if (cs<TCH-1){
            int cg = cg0+cs+1;
            int sst = rev ? (LL - 16*(cg+1)) : 16*cg;
            load_xd((cs+1) & 1, sst);
            asm volatile("cp.async.commit_group;");
            asm volatile("cp.async.wait_group 1;");
        } else {
            asm volatile("cp.async.wait_group 0;");
        }
        __syncthreads();
        int buf = cs & 1;
        {
            float4 v = *(const float4*)&s_xd[buf][tpp*16 + to4];
            float* d = &s_x2[buf][tpp];
            d[(to4  )*32] = v.x;
            d[(to4+1)*32] = v.y;
            d[(to4+2)*32] = v.z;
            d[(to4+3)*32] = v.w;
        }
        __syncthreads();
        int cg = cg0+cs;
        int sst = rev ? (LL - 16*(cg+1)) : 16*cg;
        int a0 = sst/48, b0 = sst%48;
        const float* x2 = &s_x2[buf][0];
        #pragma unroll 4
        for (int j=0;j<16;j++){
            int off = rev ? (15-j) : j;
            const float* xr = x2 + off*32;
            float4 dA = *(const float4*)(xr);
            float2 dB = *(const float2*)(xr+4);
            float draw = dtb + dtw[0]*dA.x + dtw[1]*dA.y + dtw[2]*dA.z
                             + dtw[3]*dA.w + dtw[4]*dB.x + dtw[5]*dB.y;
            float delta = (draw > 15.f) ? draw : __logf(1.f + __expf(draw));
            cum += delta;
            float4 C0 = *(const float4*)(xr+16);
            float4 C1 = *(const float4*)(xr+20);
            float y = 0.f;
            y += C0.x * (ex2f(cum*Acl[0])*hin[0]);
            y += C0.y * (ex2f(cum*Acl[1])*hin[1]);
            y += C0.z * (ex2f(cum*Acl[2])*hin[2]);
            y += C0.w * (ex2f(cum*Acl[3])*hin[3]);
            y += C1.x * (ex2f(cum*Acl[4])*hin[4]);
            y += C1.y * (ex2f(cum*Acl[5])*hin[5]);
            y += C1.z * (ex2f(cum*Acl[6])*hin[6]);
            y += C1.w * (ex2f(cum*Acl[7])*hin[7]);
            int row = kt ? ((b0+off)*48 + a0) : (sst+off);
            atomicAdd(&y_base[(size_t)row*96 + c], y);
        }
        __syncthreads();
    }
}

// =============== K4: ssln LN + p2n LN + a*z + ysum ===============
__global__ __launch_bounds__(96) void k4_comb(const float* __restrict__ g1g, const float* __restrict__ b1g,
                                              const float* __restrict__ g2g, const float* __restrict__ b2g,
                                              const int* __restrict__ bidx)
{
    __shared__ float T[48*97];
    __shared__ float mu1[48], rs1[48], mu2[48], rs2[48];
    __shared__ float G1[96], B1[96], G2[96], B2[96];
    int qb = blockIdx.x, q = qb>>4, hr = blockIdx.y, tid = threadIdx.x;
    bool even = ((bidx[0] & 1) == 0);
    G1[tid]=g1g[q*96+tid]; B1[tid]=b1g[q*96+tid];
    G2[tid]=g2g[q*96+tid]; B2[tid]=b2g[q*96+tid];
    const float* yb = g_y + (size_t)qb*LL*96;
    for (int i=tid; i<48*96; i+=96){
        int w=i/96, c=i%96;
        int pf = even ? (w*48+hr) : ((47-hr)*48+(47-w));
        T[w*97+c] = yb[(size_t)pf*96+c];
    }
    __syncthreads();
    {
        int p = tid>>1, half = tid&1;
        float s=0.f, ss=0.f;
        const float* row = &T[p*97 + half*48];
        #pragma unroll 8
        for (int c=0;c<48;c++){ float v=row[c]; s+=v; ss+=v*v; }
        s  += __shfl_xor_sync(0xffffffffu, s, 1);
        ss += __shfl_xor_sync(0xffffffffu, ss, 1);
        if (half==0){
            float m = s*(1.f/96.f);
            mu1[p]=m; rs1[p]=rsqrtf(ss*(1.f/96.f)-m*m+1e-6f);
        }
    }
    __syncthreads();
    {
        int p = tid>>1, half = tid&1;
        float m1=mu1[p], r1=rs1[p];
        float s=0.f, ss=0.f;
        const float* row = &T[p*97 + half*48];
        const float* gg = &G1[half*48];
        const float* bb = &B1[half*48];
        #pragma unroll 8
        for (int c=0;c<48;c++){ float t=(row[c]-m1)*r1*gg[c]+bb[c]; s+=t; ss+=t*t; }
        s  += __shfl_xor_sync(0xffffffffu, s, 1);
        ss += __shfl_xor_sync(0xffffffffu, ss, 1);
        if (half==0){
            float m = s*(1.f/96.f);
            mu2[p]=m; rs2[p]=rsqrtf(ss*(1.f/96.f)-m*m+1e-6f);
        }
    }
    __syncthreads();
    {
        int c = tid;
        float g1=G1[c], b1=B1[c], g2=G2[c], b2=B2[c];
        float ysum=0.f;
        const float* ab = g_a  + ((size_t)qb*LL + hr*48)*96;
        float*       yo = g_yo + ((size_t)qb*LL + hr*48)*96;
        for (int w=0; w<48; w++){
            float o = T[w*97+c];
            float t  = (o-mu1[w])*rs1[w]*g1 + b1;
            float z2 = (t-mu2[w])*rs2[w]*g2 + b2;
            float a = ab[(size_t)w*96 + c];
            float y = a*z2;
            ysum += y;
            yo[(size_t)w*96 + c] = y;
        }
        atomicAdd(&g_ysum[qb*96+c], ysum);
    }
}

// =============== K5: channel attention ===============
__global__ __launch_bounds__(96) void k5_att(const float* __restrict__ w1, const float* __restrict__ b1,
                                             const float* __restrict__ w2, const float* __restrict__ b2)
{
    __shared__ float sv[96], tv[12];
    int qb = blockIdx.x, q = qb>>4, c = threadIdx.x;
    sv[c] = g_ysum[qb*96+c] * (1.f/2304.f);
    __syncthreads();
    if (c<12){
        float acc = b1[q*12+c];
        #pragma unroll 8
        for (int cc=0; cc<96; cc++) acc += w1[(q*12+c)*96+cc]*sv[cc];
        tv[c] = siluf(acc);
    }
    __syncthreads();
    float acc = b2[q*96+c];
    #pragma unroll
    for (int r=0;r<12;r++) acc += w2[(q*96+c)*12+r]*tv[r];
    g_att[qb*96+c] = 1.f/(1.f+__expf(-acc));
}

// =============== K6: residual + att + transpose to NCHW ===============
__global__ __launch_bounds__(256) void k6_fin(const float* __restrict__ x, float* __restrict__ out)
{
    __shared__ float tile[96*49];
    __shared__ float atts[96];
    int qb = blockIdx.x, q = qb>>4, bb = qb&15, hr = blockIdx.y;
    int qh=(q>>1)*48, qw=(q&1)*48;
    const float* src = g_yo + ((size_t)qb*LL + hr*48)*96;
    for (int i=threadIdx.x; i<48*96; i+=256){
        int w=i/96, c=i%96;
        tile[c*49+w] = src[i];
    }
    for (int i=threadIdx.x; i<96; i+=256) atts[i]=g_att[qb*96+i];
    __syncthreads();
    for (int i=threadIdx.x; i<96*48; i+=256){
        int c=i/48, w=i%48;
        size_t oi = ((size_t)(bb*96+c)*96 + qh+hr)*96 + qw + w;
        out[oi] = x[oi] + tile[c*49+w]*atts[c];
    }
}

// ================================================================
extern "C" void kernel_launch(void* const* d_in, const int* in_sizes, int n_in,
                              void* d_out, int out_size)
{
    const float* x    = (const float*)d_in[0];
    const float* ln_g = (const float*)d_in[1];
    const float* ln_b = (const float*)d_in[2];
    const float* p1w  = (const float*)d_in[3];
    const float* p1b  = (const float*)d_in[4];
    const float* p2w  = (const float*)d_in[5];
    const float* p2b  = (const float*)d_in[6];
    const float* dww  = (const float*)d_in[7];
    const float* dwb  = (const float*)d_in[8];
    const float* xprj = (const float*)d_in[9];
    const float* dtw  = (const float*)d_in[10];
    const float* dtb  = (const float*)d_in[11];
    const float* alog = (const float*)d_in[12];
    const float* dsv  = (const float*)d_in[13];
    const float* ssg  = (const float*)d_in[14];
    const float* ssb  = (const float*)d_in[15];
    const float* png  = (const float*)d_in[16];
    const float* pnb  = (const float*)d_in[17];
    const float* cw1  = (const float*)d_in[18];
    const float* cb1  = (const float*)d_in[19];
    const float* cw2  = (const float*)d_in[20];
    const float* cb2  = (const float*)d_in[21];
    const int*   bidx = (const int*)  d_in[22];
    float* out = (float*)d_out;

    const int smem_k1 = (96*X1S + 96*W1S)*4;
    const int smem_k2 = 3*48*96*4;
    const int smem_k3 = (96*K3XS + 96*K3WS)*4;
    cudaFuncSetAttribute(k1_gemm, cudaFuncAttributeMaxDynamicSharedMemorySize, smem_k1);
    cudaFuncSetAttribute(k2_dw,   cudaFuncAttributeMaxDynamicSharedMemorySize, smem_k2);
    cudaFuncSetAttribute(k3_proj, cudaFuncAttributeMaxDynamicSharedMemorySize, smem_k3);

    k1_gemm<<<dim3(576,4), 256, smem_k1>>>(x, ln_g, ln_b, p1w, p1b, p2w, p2b);
    k2_dw  <<<dim3(64,48), 256, smem_k2>>>(dww, dwb, bidx);
    k3_proj<<<dim3(288,2,4), 256, smem_k3>>>(xprj);
    k_scan_seg   <<<dim3(64,4,NSEG), 96>>>(dtw, dtb, alog, dsv);
    k_scan_prefix<<<dim3(64,4), 96>>>(alog);
    k_scan_fix   <<<dim3(64,4,NSEG-1), 96>>>(dtw, dtb, alog);
    k4_comb<<<dim3(64,48), 96>>>(ssg, ssb, png, pnb, bidx);
    k5_att <<<64, 96>>>(cw1, cb1, cw2, cb2);
    k6_fin <<<dim3(64,48), 256>>>(x, out);
}